// round 14
// baseline (speedup 1.0000x reference)
#include <cuda_runtime.h>
#include <cuda_fp16.h>
#include <cstdint>

// Problem constants
#define BATCH 8
#define HH 96
#define WW 96
#define CC 128
#define LL (HH*WW)            // 9216
#define ROWS (BATCH*LL)       // 73728
#define NWIN 144
#define WS 8
#define NTOK 64
#define HEADS 4
#define HD 32
#define QKSCALE 0.17677669529663687f

// ---------------- scratch -----------------
__device__ __half g_xw [ (size_t)ROWS*CC ];
__device__ __half g_qkv[ (size_t)ROWS*3*CC ];
__device__ __half g_att[ (size_t)ROWS*CC ];
__device__ float  g_xa [ (size_t)ROWS*CC ];
__device__ float  g_xb [ (size_t)ROWS*CC ];
__device__ __half g_wt [ 524288 ];

__device__ __forceinline__ uint32_t smem_u32(const void* p) {
    uint32_t a;
    asm("{ .reg .u64 t; cvta.to.shared.u64 t, %1; cvt.u32.u64 %0, t; }" : "=r"(a) : "l"(p));
    return a;
}
__device__ __forceinline__ float gelu_exact(float x) {
    return 0.5f * x * (1.f + erff(x * 0.70710678118654752f));
}
__device__ __forceinline__ uint2 f4_to_h4(float4 v) {
    union { uint2 u; __half2 h[2]; } cv;
    cv.h[0] = __floats2half2_rn(v.x, v.y);
    cv.h[1] = __floats2half2_rn(v.z, v.w);
    return cv.u;
}
__device__ __forceinline__ uint32_t h2pack(float a, float b) {
    union { uint32_t u; __half2 h; } cv;
    cv.h = __floats2half2_rn(a, b);
    return cv.u;
}

#define LDSM4(r, addr) \
    asm volatile("ldmatrix.sync.aligned.m8n8.x4.shared.b16 {%0,%1,%2,%3},[%4];" \
        : "=r"((r)[0]), "=r"((r)[1]), "=r"((r)[2]), "=r"((r)[3]) : "r"(addr))
#define LDSM4T(r, addr) \
    asm volatile("ldmatrix.sync.aligned.m8n8.x4.trans.shared.b16 {%0,%1,%2,%3},[%4];" \
        : "=r"((r)[0]), "=r"((r)[1]), "=r"((r)[2]), "=r"((r)[3]) : "r"(addr))
#define MMA16816(acc, a, b0, b1) \
    asm volatile("mma.sync.aligned.m16n8k16.row.col.f32.f16.f16.f32 " \
        "{%0,%1,%2,%3},{%4,%5,%6,%7},{%8,%9},{%0,%1,%2,%3};" \
        : "+f"((acc)[0]), "+f"((acc)[1]), "+f"((acc)[2]), "+f"((acc)[3]) \
        : "r"((a)[0]), "r"((a)[1]), "r"((a)[2]), "r"((a)[3]), "r"(b0), "r"(b1))

// ---------------- LayerNorm gather (block-a entry only) ----------------------
template<bool GATHER>
__global__ __launch_bounds__(128) void ln_kernel(
    const float* __restrict__ x, const float* __restrict__ gam,
    const float* __restrict__ bet, __half* __restrict__ out, int shift)
{
    int lane = threadIdx.x & 31;
    int warp = threadIdx.x >> 5;
    int r = blockIdx.x * 4 + warp;
    const float* src;
    if (GATHER) {
        int wi = r >> 6, n = r & 63;
        int b  = wi / NWIN, wl = wi % NWIN;
        int whi = wl / 12, wwi = wl % 12;
        int h0 = whi * 8 + (n >> 3), w0 = wwi * 8 + (n & 7);
        int hs = h0 + shift; if (hs >= HH) hs -= HH;
        int ws_ = w0 + shift; if (ws_ >= WW) ws_ -= WW;
        src = &x[(size_t)(b * LL + hs * WW + ws_) * CC];
    } else {
        src = &x[(size_t)r * CC];
    }
    float4 v = *(const float4*)&src[lane * 4];
    float s1 = v.x + v.y + v.z + v.w;
    float s2 = v.x*v.x + v.y*v.y + v.z*v.z + v.w*v.w;
    #pragma unroll
    for (int o = 16; o; o >>= 1) {
        s1 += __shfl_xor_sync(0xffffffffu, s1, o);
        s2 += __shfl_xor_sync(0xffffffffu, s2, o);
    }
    float mean = s1 * (1.f / CC);
    float var  = s2 * (1.f / CC) - mean * mean;
    float rstd = rsqrtf(var + 1e-5f);
    float4 g4 = *(const float4*)&gam[lane * 4];
    float4 b4 = *(const float4*)&bet[lane * 4];
    float4 o4;
    o4.x = (v.x - mean) * rstd * g4.x + b4.x;
    o4.y = (v.y - mean) * rstd * g4.y + b4.y;
    o4.z = (v.z - mean) * rstd * g4.z + b4.z;
    o4.w = (v.w - mean) * rstd * g4.w + b4.w;
    *(uint2*)&out[(size_t)r * CC + lane * 4] = f4_to_h4(o4);
}

// ---------------- batched weight transpose ----------------------------------
struct TPJobs {
    const float* src[9];
    __half* dst[9];
    int K[9];
    int N[9];
};
__global__ __launch_bounds__(256) void transpose_all(TPJobs jb)
{
    __shared__ float t[32][33];
    int m = blockIdx.z;
    int K = jb.K[m], N = jb.N[m];
    int k0 = blockIdx.x * 32, n0 = blockIdx.y * 32;
    if (k0 >= K || n0 >= N) return;
    const float* src = jb.src[m];
    __half* dst = jb.dst[m];
    int x = threadIdx.x & 31, y = threadIdx.x >> 5;
    #pragma unroll
    for (int i = 0; i < 32; i += 8)
        t[y + i][x] = src[(size_t)(k0 + y + i) * N + n0 + x];
    __syncthreads();
    #pragma unroll
    for (int i = 0; i < 32; i += 8)
        dst[(size_t)(n0 + y + i) * K + k0 + x] = __float2half_rn(t[x][y + i]);
}

// ---------------- shared GEMM plumbing (k32-chunk path) ----------------------
#define AS_STRIDE 40
#define TILE_H   (128*AS_STRIDE)
#define GM_SMEM  (4*TILE_H*2)              // 40960 bytes

__device__ __forceinline__ void copy_chunk(
    const __half* __restrict__ A, const __half* __restrict__ B,
    int bm, int bn, int K, int k0, __half* sA, __half* sB, int tid)
{
    uint32_t a_s = smem_u32(sA), b_s = smem_u32(sB);
    #pragma unroll
    for (int i = 0; i < 2; i++) {
        int idx = tid + i * 256;
        int row = idx >> 2, q = idx & 3;
        const __half* ga = &A[(size_t)(bm + row) * K + k0 + q * 8];
        const __half* gb = &B[(size_t)(bn + row) * K + k0 + q * 8];
        uint32_t so = (row * AS_STRIDE + q * 8) * 2;
        asm volatile("cp.async.cg.shared.global [%0],[%1],16;" :: "r"(a_s + so), "l"(ga));
        asm volatile("cp.async.cg.shared.global [%0],[%1],16;" :: "r"(b_s + so), "l"(gb));
    }
    asm volatile("cp.async.commit_group;" ::: "memory");
}

// ---------------- general GEMM (EPI 0:+bias | 4:plain) -----------------------
template<int EPI, typename OT>
__global__ __launch_bounds__(256)
void gemm_mma(const __half* __restrict__ A, const __half* __restrict__ B,
              const float* __restrict__ bias, OT* __restrict__ C,
              const float* __restrict__ res, int M, int N, int K, int shift)
{
    extern __shared__ __half smh[];
    __half* bufA[2] = { smh,          smh + 2*TILE_H };
    __half* bufB[2] = { smh + TILE_H, smh + 3*TILE_H };
    int tid = threadIdx.x, lane = tid & 31, wid = tid >> 5;
    int g = lane >> 2, kq = lane & 3;
    int warpM = wid & 3, warpN = wid >> 2;
    int bm = blockIdx.x * 128, bn = blockIdx.y * 128;

    float acc[2][8][4];
    #pragma unroll
    for (int i = 0; i < 2; i++)
        #pragma unroll
        for (int j = 0; j < 8; j++)
            #pragma unroll
            for (int q = 0; q < 4; q++) acc[i][j][q] = 0.f;

    int nc = K >> 5;
    copy_chunk(A, B, bm, bn, K, 0, bufA[0], bufB[0], tid);

    uint32_t a_off = (((warpM * 32 + (lane & 15)) * AS_STRIDE) + ((lane >> 4) << 3)) * 2;
    uint32_t b_off = (((warpN * 64 + (lane & 7) + (((lane >> 4) & 1) << 3)) * AS_STRIDE)
                     + (((lane >> 3) & 1) << 3)) * 2;

    for (int c = 0; c < nc; c++) {
        if (c + 1 < nc) {
            copy_chunk(A, B, bm, bn, K, (c + 1) << 5, bufA[(c+1)&1], bufB[(c+1)&1], tid);
            asm volatile("cp.async.wait_group 1;" ::: "memory");
        } else {
            asm volatile("cp.async.wait_group 0;" ::: "memory");
        }
        __syncthreads();

        uint32_t ab = smem_u32(bufA[c&1]) + a_off;
        uint32_t bb = smem_u32(bufB[c&1]) + b_off;
        #pragma unroll
        for (int ks = 0; ks < 2; ks++) {
            uint32_t a[2][4], b[4][4];
            LDSM4(a[0], ab + ks * 32);
            LDSM4(a[1], ab + 16 * AS_STRIDE * 2 + ks * 32);
            #pragma unroll
            for (int j16 = 0; j16 < 4; j16++)
                LDSM4(b[j16], bb + j16 * 16 * AS_STRIDE * 2 + ks * 32);
            #pragma unroll
            for (int i = 0; i < 2; i++)
                #pragma unroll
                for (int j = 0; j < 8; j++) {
                    uint32_t b0 = b[j >> 1][(j & 1) * 2];
                    uint32_t b1 = b[j >> 1][(j & 1) * 2 + 1];
                    MMA16816(acc[i][j], a[i], b0, b1);
                }
        }
        __syncthreads();
    }

    #pragma unroll
    for (int i = 0; i < 2; i++) {
        #pragma unroll
        for (int rr = 0; rr < 2; rr++) {
            int gr = bm + warpM * 32 + i * 16 + g + rr * 8;
            #pragma unroll
            for (int j = 0; j < 8; j++) {
                int col = bn + warpN * 64 + j * 8 + 2 * kq;
                float vx = acc[i][j][rr*2+0];
                float vy = acc[i][j][rr*2+1];
                if (EPI != 4) {
                    vx += __ldg(&bias[col]);
                    vy += __ldg(&bias[col+1]);
                }
                if (sizeof(OT) == 2) {
                    *(__half2*)&((__half*)C)[(size_t)gr * N + col] = __floats2half2_rn(vx, vy);
                } else {
                    *(float2*)&((float*)C)[(size_t)gr * N + col] = make_float2(vx, vy);
                }
            }
        }
    }
}

// ---------------- wide GEMM: K=128, A resident full-K (R9-proven) ------------
#define AW_STRIDE 136
#define AW_TILE   (128*AW_STRIDE)
#define GW_SMEM   (3*AW_TILE*2)             // 104448 bytes

template<int EPI>
__global__ __launch_bounds__(256)
void gemm_wide(const __half* __restrict__ A, const __half* __restrict__ B,
               const float* __restrict__ bias, __half* __restrict__ C,
               int N, int nt)
{
    extern __shared__ __half smh[];
    __half* sA = smh;
    __half* sB[2] = { smh + AW_TILE, smh + 2*AW_TILE };
    int tid = threadIdx.x, lane = tid & 31, wid = tid >> 5;
    int g = lane >> 2, kq = lane & 3;
    int warpM = wid & 3, warpN = wid >> 2;
    int bm = blockIdx.x * 128;

    {
        uint32_t a_s = smem_u32(sA), b_s = smem_u32(sB[0]);
        #pragma unroll
        for (int i = 0; i < 8; i++) {
            int idx = tid + i * 256;
            int row = idx >> 4, q = idx & 15;
            uint32_t so = (row * AW_STRIDE + q * 8) * 2;
            asm volatile("cp.async.cg.shared.global [%0],[%1],16;"
                :: "r"(a_s + so), "l"(&A[(size_t)(bm + row) * 128 + q * 8]));
            asm volatile("cp.async.cg.shared.global [%0],[%1],16;"
                :: "r"(b_s + so), "l"(&B[(size_t)row * 128 + q * 8]));
        }
        asm volatile("cp.async.commit_group;" ::: "memory");
        if (nt > 1) {
            uint32_t b1_s = smem_u32(sB[1]);
            #pragma unroll
            for (int i = 0; i < 8; i++) {
                int idx = tid + i * 256;
                int row = idx >> 4, q = idx & 15;
                uint32_t so = (row * AW_STRIDE + q * 8) * 2;
                asm volatile("cp.async.cg.shared.global [%0],[%1],16;"
                    :: "r"(b1_s + so), "l"(&B[(size_t)(128 + row) * 128 + q * 8]));
            }
            asm volatile("cp.async.commit_group;" ::: "memory");
        }
    }

    uint32_t a_off = (((warpM * 32 + (lane & 15)) * AW_STRIDE) + ((lane >> 4) << 3)) * 2;
    uint32_t b_off = (((warpN * 64 + (lane & 7) + (((lane >> 4) & 1) << 3)) * AW_STRIDE)
                     + (((lane >> 3) & 1) << 3)) * 2;
    uint32_t ab = smem_u32(sA) + a_off;

    for (int bn = 0; bn < nt; bn++) {
        if (bn + 1 < nt)
            asm volatile("cp.async.wait_group 1;" ::: "memory");
        else
            asm volatile("cp.async.wait_group 0;" ::: "memory");
        __syncthreads();

        float acc[2][8][4];
        #pragma unroll
        for (int i = 0; i < 2; i++)
            #pragma unroll
            for (int j = 0; j < 8; j++)
                #pragma unroll
                for (int q = 0; q < 4; q++) acc[i][j][q] = 0.f;

        uint32_t bb = smem_u32(sB[bn & 1]) + b_off;
        #pragma unroll
        for (int ks = 0; ks < 8; ks++) {
            uint32_t a[2][4], b[4][4];
            LDSM4(a[0], ab + ks * 32);
            LDSM4(a[1], ab + 16 * AW_STRIDE * 2 + ks * 32);
            #pragma unroll
            for (int j16 = 0; j16 < 4; j16++)
                LDSM4(b[j16], bb + j16 * 16 * AW_STRIDE * 2 + ks * 32);
            #pragma unroll
            for (int i = 0; i < 2; i++)
                #pragma unroll
                for (int j = 0; j < 8; j++) {
                    uint32_t b0 = b[j >> 1][(j & 1) * 2];
                    uint32_t b1 = b[j >> 1][(j & 1) * 2 + 1];
                    MMA16816(acc[i][j], a[i], b0, b1);
                }
        }

        #pragma unroll
        for (int i = 0; i < 2; i++) {
            #pragma unroll
            for (int rr = 0; rr < 2; rr++) {
                int gr = bm + warpM * 32 + i * 16 + g + rr * 8;
                #pragma unroll
                for (int j = 0; j < 8; j++) {
                    int col = bn * 128 + warpN * 64 + j * 8 + 2 * kq;
                    float vx = acc[i][j][rr*2+0] + __ldg(&bias[col]);
                    float vy = acc[i][j][rr*2+1] + __ldg(&bias[col+1]);
                    if (EPI == 2) { vx = gelu_exact(vx); vy = gelu_exact(vy); }
                    *(__half2*)&C[(size_t)gr * N + col] = __floats2half2_rn(vx, vy);
                }
            }
        }

        if (bn + 2 < nt) {
            __syncthreads();
            uint32_t bs = smem_u32(sB[bn & 1]);
            #pragma unroll
            for (int i = 0; i < 8; i++) {
                int idx = tid + i * 256;
                int row = idx >> 4, q = idx & 15;
                uint32_t so = (row * AW_STRIDE + q * 8) * 2;
                asm volatile("cp.async.cg.shared.global [%0],[%1],16;"
                    :: "r"(bs + so), "l"(&B[(size_t)((bn + 2) * 128 + row) * 128 + q * 8]));
            }
            asm volatile("cp.async.commit_group;" ::: "memory");
        } else {
            __syncthreads();
        }
    }
}

// ---------------- proj GEMM + residual + LN (R9-proven 16x128 tile) ----------
__global__ __launch_bounds__(256)
void gemm_ln(const __half* __restrict__ A, const __half* __restrict__ B,
             const float* __restrict__ bias, float* __restrict__ C,
             const float* __restrict__ res, const float* __restrict__ gam,
             const float* __restrict__ bet, __half* __restrict__ lnout,
             int K, int shift)
{
    extern __shared__ __half smh[];
    __half* bufA[2] = { smh,          smh + 2*TILE_H };
    __half* bufB[2] = { smh + TILE_H, smh + 3*TILE_H };
    int tid = threadIdx.x, lane = tid & 31, wid = tid >> 5;
    int g = lane >> 2, kq = lane & 3;
    int bm = blockIdx.x * 128;

    float acc[16][4];
    #pragma unroll
    for (int j = 0; j < 16; j++)
        #pragma unroll
        for (int q = 0; q < 4; q++) acc[j][q] = 0.f;

    int nc = K >> 5;
    copy_chunk(A, B, bm, 0, K, 0, bufA[0], bufB[0], tid);

    uint32_t a_off = (((wid * 16 + (lane & 15)) * AS_STRIDE) + ((lane >> 4) << 3)) * 2;
    uint32_t b_off = ((((lane & 7) + (((lane >> 4) & 1) << 3)) * AS_STRIDE)
                     + (((lane >> 3) & 1) << 3)) * 2;

    for (int c = 0; c < nc; c++) {
        if (c + 1 < nc) {
            copy_chunk(A, B, bm, 0, K, (c + 1) << 5, bufA[(c+1)&1], bufB[(c+1)&1], tid);
            asm volatile("cp.async.wait_group 1;" ::: "memory");
        } else {
            asm volatile("cp.async.wait_group 0;" ::: "memory");
        }
        __syncthreads();

        uint32_t ab = smem_u32(bufA[c&1]) + a_off;
        uint32_t bb = smem_u32(bufB[c&1]) + b_off;
        #pragma unroll
        for (int ks = 0; ks < 2; ks++) {
            uint32_t a[4];
            LDSM4(a, ab + ks * 32);
            #pragma unroll
            for (int j16 = 0; j16 < 8; j16++) {
                uint32_t b[4];
                LDSM4(b, bb + j16 * 16 * AS_STRIDE * 2 + ks * 32);
                MMA16816(acc[2*j16],   a, b[0], b[1]);
                MMA16816(acc[2*j16+1], a, b[2], b[3]);
            }
        }
        __syncthreads();
    }

    int r0 = bm + wid * 16 + g;
    int r1 = r0 + 8;
    int dst0, dst1;
    {
        int d[2];
        #pragma unroll
        for (int rr = 0; rr < 2; rr++) {
            int gr = rr ? r1 : r0;
            int wi = gr >> 6, n = gr & 63;
            int b  = wi / NWIN, wl = wi % NWIN;
            int whi = wl / 12, wwi = wl % 12;
            int h0 = whi * 8 + (n >> 3), w0 = wwi * 8 + (n & 7);
            int h = h0 + shift; if (h >= HH) h -= HH;
            int w = w0 + shift; if (w >= WW) w -= WW;
            d[rr] = b * LL + h * WW + w;
        }
        dst0 = d[0]; dst1 = d[1];
    }

    float vv[16][4];
    float s1a = 0.f, s2a = 0.f, s1b = 0.f, s2b = 0.f;
    #pragma unroll
    for (int j = 0; j < 16; j++) {
        int col = j * 8 + 2 * kq;
        float bx = __ldg(&bias[col]), by = __ldg(&bias[col+1]);
        float2 ra = *(const float2*)&res[(size_t)dst0 * CC + col];
        float2 rb = *(const float2*)&res[(size_t)dst1 * CC + col];
        float v0 = acc[j][0] + bx + ra.x;
        float v1 = acc[j][1] + by + ra.y;
        float v2 = acc[j][2] + bx + rb.x;
        float v3 = acc[j][3] + by + rb.y;
        vv[j][0] = v0; vv[j][1] = v1; vv[j][2] = v2; vv[j][3] = v3;
        *(float2*)&C[(size_t)dst0 * CC + col] = make_float2(v0, v1);
        *(float2*)&C[(size_t)dst1 * CC + col] = make_float2(v2, v3);
        s1a += v0 + v1; s2a += v0*v0 + v1*v1;
        s1b += v2 + v3; s2b += v2*v2 + v3*v3;
    }

    s1a += __shfl_xor_sync(0xffffffffu, s1a, 1);
    s1a += __shfl_xor_sync(0xffffffffu, s1a, 2);
    s2a += __shfl_xor_sync(0xffffffffu, s2a, 1);
    s2a += __shfl_xor_sync(0xffffffffu, s2a, 2);
    s1b += __shfl_xor_sync(0xffffffffu, s1b, 1);
    s1b += __shfl_xor_sync(0xffffffffu, s1b, 2);
    s2b += __shfl_xor_sync(0xffffffffu, s2b, 1);
    s2b += __shfl_xor_sync(0xffffffffu, s2b, 2);

    float ma = s1a * (1.f/CC), va = s2a * (1.f/CC) - ma*ma;
    float mb = s1b * (1.f/CC), vb = s2b * (1.f/CC) - mb*mb;
    float ra_ = rsqrtf(va + 1e-5f), rb_ = rsqrtf(vb + 1e-5f);

    #pragma unroll
    for (int j = 0; j < 16; j++) {
        int col = j * 8 + 2 * kq;
        float gx = __ldg(&gam[col]), gy = __ldg(&gam[col+1]);
        float bx = __ldg(&bet[col]), by = __ldg(&bet[col+1]);
        *(__half2*)&lnout[(size_t)dst0 * CC + col] =
            __floats2half2_rn((vv[j][0]-ma)*ra_*gx+bx, (vv[j][1]-ma)*ra_*gy+by);
        *(__half2*)&lnout[(size_t)dst1 * CC + col] =
            __floats2half2_rn((vv[j][2]-mb)*rb_*gx+bx, (vv[j][3]-mb)*rb_*gy+by);
    }
}

// ---------------- fused MLP: fc1 + GELU + fc2, h stays in smem ----------------
// lnout MUST NOT alias A (cross-CTA scatter).
#define MLP_SMEM (4*AW_TILE*2 + 2048)

template<int MODE>
__global__ __launch_bounds__(256)
void gemm_mlp(const __half* __restrict__ A, const __half* __restrict__ W1,
              const __half* __restrict__ W2,
              const float* __restrict__ b1, const float* __restrict__ b2,
              float* __restrict__ C, const float* __restrict__ res,
              const float* __restrict__ gam, const float* __restrict__ bet,
              __half* __restrict__ lnout)
{
    extern __shared__ __half smh[];
    __half* sX  = smh;
    __half* sH  = smh + AW_TILE;
    __half* sW1 = smh + 2*AW_TILE;
    __half* sW2 = smh + 3*AW_TILE;
    float* part = (float*)(smh + 4*AW_TILE);
    int tid = threadIdx.x, lane = tid & 31, wid = tid >> 5;
    int g = lane >> 2, kq = lane & 3;
    int warpM = wid & 3, warpN = wid >> 2;
    int bm = blockIdx.x * 128;

    {
        uint32_t x_s = smem_u32(sX), w1_s = smem_u32(sW1), w2_s = smem_u32(sW2);
        #pragma unroll
        for (int i = 0; i < 8; i++) {
            int idx = tid + i * 256;
            int row = idx >> 4, q = idx & 15;
            uint32_t so = (row * AW_STRIDE + q * 8) * 2;
            asm volatile("cp.async.cg.shared.global [%0],[%1],16;"
                :: "r"(x_s + so), "l"(&A[(size_t)(bm + row) * 128 + q * 8]));
            asm volatile("cp.async.cg.shared.global [%0],[%1],16;"
                :: "r"(w1_s + so), "l"(&W1[(size_t)row * 128 + q * 8]));
            asm volatile("cp.async.cg.shared.global [%0],[%1],16;"
                :: "r"(w2_s + so), "l"(&W2[(size_t)row * 512 + q * 8]));
        }
        asm volatile("cp.async.commit_group;" ::: "memory");
    }

    uint32_t a_off = (((warpM * 32 + (lane & 15)) * AW_STRIDE) + ((lane >> 4) << 3)) * 2;
    uint32_t b_off = (((warpN * 64 + (lane & 7) + (((lane >> 4) & 1) << 3)) * AW_STRIDE)
                     + (((lane >> 3) & 1) << 3)) * 2;
    uint32_t xab = smem_u32(sX) + a_off;
    uint32_t hab = smem_u32(sH) + a_off;
    uint32_t w1b = smem_u32(sW1) + b_off;
    uint32_t w2b = smem_u32(sW2) + b_off;

    float cacc[2][8][4];
    #pragma unroll
    for (int i = 0; i < 2; i++)
        #pragma unroll
        for (int j = 0; j < 8; j++)
            #pragma unroll
            for (int q = 0; q < 4; q++) cacc[i][j][q] = 0.f;

    for (int c = 0; c < 4; c++) {
        asm volatile("cp.async.wait_group 0;" ::: "memory");
        __syncthreads();

        // stage 1: S = X @ W1c^T
        float sacc[2][8][4];
        #pragma unroll
        for (int i = 0; i < 2; i++)
            #pragma unroll
            for (int j = 0; j < 8; j++)
                #pragma unroll
                for (int q = 0; q < 4; q++) sacc[i][j][q] = 0.f;
        #pragma unroll
        for (int ks = 0; ks < 8; ks++) {
            uint32_t a[2][4], b[4][4];
            LDSM4(a[0], xab + ks * 32);
            LDSM4(a[1], xab + 16 * AW_STRIDE * 2 + ks * 32);
            #pragma unroll
            for (int j16 = 0; j16 < 4; j16++)
                LDSM4(b[j16], w1b + j16 * 16 * AW_STRIDE * 2 + ks * 32);
            #pragma unroll
            for (int i = 0; i < 2; i++)
                #pragma unroll
                for (int j = 0; j < 8; j++) {
                    uint32_t b0 = b[j >> 1][(j & 1) * 2];
                    uint32_t b1r = b[j >> 1][(j & 1) * 2 + 1];
                    MMA16816(sacc[i][j], a[i], b0, b1r);
                }
        }
        // GELU + store h chunk to smem
        #pragma unroll
        for (int i = 0; i < 2; i++)
            #pragma unroll
            for (int rr = 0; rr < 2; rr++) {
                int row = warpM * 32 + i * 16 + g + rr * 8;
                #pragma unroll
                for (int j = 0; j < 8; j++) {
                    int col = warpN * 64 + j * 8 + 2 * kq;
                    float bx = __ldg(&b1[c * 128 + col]);
                    float by = __ldg(&b1[c * 128 + col + 1]);
                    float vx = gelu_exact(sacc[i][j][rr*2+0] + bx);
                    float vy = gelu_exact(sacc[i][j][rr*2+1] + by);
                    *(__half2*)&sH[row * AW_STRIDE + col] = __floats2half2_rn(vx, vy);
                }
            }
        __syncthreads();   // sH complete; sW1 free

        if (c + 1 < 4) {
            uint32_t w1_s = smem_u32(sW1);
            #pragma unroll
            for (int i = 0; i < 8; i++) {
                int idx = tid + i * 256;
                int row = idx >> 4, q = idx & 15;
                uint32_t so = (row * AW_STRIDE + q * 8) * 2;
                asm volatile("cp.async.cg.shared.global [%0],[%1],16;"
                    :: "r"(w1_s + so), "l"(&W1[(size_t)((c + 1) * 128 + row) * 128 + q * 8]));
            }
            asm volatile("cp.async.commit_group;" ::: "memory");
        }

        // stage 2: C += H @ W2c^T
        #pragma unroll
        for (int ks = 0; ks < 8; ks++) {
            uint32_t a[2][4], b[4][4];
            LDSM4(a[0], hab + ks * 32);
            LDSM4(a[1], hab + 16 * AW_STRIDE * 2 + ks * 32);
            #pragma unroll
            for (int j16 = 0; j16 < 4; j16++)
                LDSM4(b[j16], w2b + j16 * 16 * AW_STRIDE * 2 + ks * 32);
            #pragma unroll
            for (int i = 0; i < 2; i++)
                #pragma unroll
                for (int j = 0; j < 8; j++) {
                    uint32_t b0 = b[j >> 1][(j & 1) * 2];
                    uint32_t b1r = b[j >> 1][(j & 1) * 2 + 1];
                    MMA16816(cacc[i][j], a[i], b0, b1r);
                }
        }
        __syncthreads();   // sW2, sH free

        if (c + 1 < 4) {
            uint32_t w2_s = smem_u32(sW2);
            #pragma unroll
            for (int i = 0; i < 8; i++) {
                int idx = tid + i * 256;
                int row = idx >> 4, q = idx & 15;
                uint32_t so = (row * AW_STRIDE + q * 8) * 2;
                asm volatile("cp.async.cg.shared.global [%0],[%1],16;"
                    :: "r"(w2_s + so), "l"(&W2[(size_t)row * 512 + (c + 1) * 128 + q * 8]));
            }
            asm volatile("cp.async.commit_group;" ::: "memory");
        }
    }

    // epilogue: +b2, +res -> C; optional LN -> lnout
    int dstA[2][2], lnA[2][2];
    #pragma unroll
    for (int i = 0; i < 2; i++)
        #pragma unroll
        for (int rr = 0; rr < 2; rr++) {
            int gr = bm + warpM * 32 + i * 16 + g + rr * 8;
            dstA[i][rr] = gr;
            if (MODE == 1) {
                int b = gr / LL, rem = gr % LL;
                int h = rem / WW, w = rem % WW;
                int h0 = h - 4; if (h0 < 0) h0 += HH;
                int w0 = w - 4; if (w0 < 0) w0 += WW;
                lnA[i][rr] = b * LL + ((h0 >> 3) * 12 + (w0 >> 3)) * 64 + (h0 & 7) * 8 + (w0 & 7);
            }
        }

    float s1[2][2] = {{0.f,0.f},{0.f,0.f}};
    float s2[2][2] = {{0.f,0.f},{0.f,0.f}};
    #pragma unroll
    for (int i = 0; i < 2; i++)
        #pragma unroll
        for (int j = 0; j < 8; j++) {
            int col = warpN * 64 + j * 8 + 2 * kq;
            float bx = __ldg(&b2[col]), by = __ldg(&b2[col+1]);
            #pragma unroll
            for (int rr = 0; rr < 2; rr++) {
                float2 rv = *(const float2*)&res[(size_t)dstA[i][rr] * CC + col];
                float v0 = cacc[i][j][rr*2+0] + bx + rv.x;
                float v1 = cacc[i][j][rr*2+1] + by + rv.y;
                cacc[i][j][rr*2+0] = v0;
                cacc[i][j][rr*2+1] = v1;
                *(float2*)&C[(size_t)dstA[i][rr] * CC + col] = make_float2(v0, v1);
                if (MODE == 1) { s1[i][rr] += v0 + v1; s2[i][rr] += v0*v0 + v1*v1; }
            }
        }
    if (MODE == 2) return;

    #pragma unroll
    for (int i = 0; i < 2; i++)
        #pragma unroll
        for (int rr = 0; rr < 2; rr++) {
            s1[i][rr] += __shfl_xor_sync(0xffffffffu, s1[i][rr], 1);
            s1[i][rr] += __shfl_xor_sync(0xffffffffu, s1[i][rr], 2);
            s2[i][rr] += __shfl_xor_sync(0xffffffffu, s2[i][rr], 1);
            s2[i][rr] += __shfl_xor_sync(0xffffffffu, s2[i][rr], 2);
        }
    if (kq == 0) {
        #pragma unroll
        for (int i = 0; i < 2; i++)
            #pragma unroll
            for (int rr = 0; rr < 2; rr++) {
                int rl = warpM * 32 + i * 16 + g + rr * 8;
                part[rl * 4 + warpN * 2 + 0] = s1[i][rr];
                part[rl * 4 + warpN * 2 + 1] = s2[i][rr];
            }
    }
    __syncthreads();

    #pragma unroll
    for (int i = 0; i < 2; i++)
        #pragma unroll
        for (int rr = 0; rr < 2; rr++) {
            int rl = warpM * 32 + i * 16 + g + rr * 8;
            float t1 = s1[i][rr] + part[rl * 4 + (1 - warpN) * 2 + 0];
            float t2 = s2[i][rr] + part[rl * 4 + (1 - warpN) * 2 + 1];
            float m = t1 * (1.f / CC);
            float v = t2 * (1.f / CC) - m * m;
            float rs = rsqrtf(v + 1e-5f);
            #pragma unroll
            for (int j = 0; j < 8; j++) {
                int col = warpN * 64 + j * 8 + 2 * kq;
                float gx = __ldg(&gam[col]), gy = __ldg(&gam[col+1]);
                float bx = __ldg(&bet[col]), by = __ldg(&bet[col+1]);
                *(__half2*)&lnout[(size_t)lnA[i][rr] * CC + col] =
                    __floats2half2_rn((cacc[i][j][rr*2+0] - m) * rs * gx + bx,
                                      (cacc[i][j][rr*2+1] - m) * rs * gy + by);
            }
        }
}

// ---------------- MMA windowed attention (conflict-free stride 392) ----------
#define AT_STRIDE 392
#define AT_SMEM   (64*AT_STRIDE*2 + 64*4)   // 50432 bytes

template<bool SHIFTED>
__global__ __launch_bounds__(128) void attn_mma(
    const __half* __restrict__ qkv, __half* __restrict__ out)
{
    extern __shared__ __half smw[];
    int* lab = (int*)(smw + 64*AT_STRIDE);
    int tid = threadIdx.x, lane = tid & 31, h = tid >> 5;
    int wi = blockIdx.x;

    const uint4* gsrc = (const uint4*)(qkv + (size_t)wi * 64 * 384);
    #pragma unroll
    for (int i = 0; i < 24; i++) {
        int idx = tid + i * 128;
        int row = idx / 48, seg = idx % 48;
        *(uint4*)&smw[row * AT_STRIDE + seg * 8] = gsrc[row * 48 + seg];
    }
    if (SHIFTED && tid < 64) {
        int wl = wi % NWIN;
        int whi = wl / 12, wwi = wl % 12;
        int hh = whi * 8 + (tid >> 3), ww_ = wwi * 8 + (tid & 7);
        int hr = (hh < HH - WS) ? 0 : ((hh < HH - 4) ? 1 : 2);
        int wr = (ww_ < WW - WS) ? 0 : ((ww_ < WW - 4) ? 1 : 2);
        lab[tid] = hr * 3 + wr;
    }
    __syncthreads();

    uint32_t sbase = smem_u32(smw);
    int qbase = h * 32;
    int kbase = 128 + h * 32;
    int vbase = 256 + h * 32;

    uint32_t q_row  = lane & 15;
    uint32_t q_colh = (lane >> 4) << 3;
    uint32_t k_row  = (lane & 7) + (((lane >> 4) & 1) << 3);
    uint32_t k_colh = ((lane >> 3) & 1) << 3;
    uint32_t v_row  = lane & 15;
    uint32_t v_colh = (lane >> 4) << 3;

    #pragma unroll
    for (int mt = 0; mt < 4; mt++) {
        float sAcc[8][4];
        #pragma unroll
        for (int j = 0; j < 8; j++)
            #pragma unroll
            for (int q = 0; q < 4; q++) sAcc[j][q] = 0.f;
        #pragma unroll
        for (int kt = 0; kt < 2; kt++) {
            uint32_t a[4];
            LDSM4(a, sbase + ((mt*16 + q_row) * AT_STRIDE + qbase + q_colh + kt*16) * 2);
            #pragma unroll
            for (int j16 = 0; j16 < 4; j16++) {
                uint32_t b[4];
                LDSM4(b, sbase + ((j16*16 + k_row) * AT_STRIDE + kbase + k_colh + kt*16) * 2);
                MMA16816(sAcc[2*j16],   a, b[0], b[1]);
                MMA16816(sAcc[2*j16+1], a, b[2], b[3]);
            }
        }

        int row_lo = mt*16 + (lane >> 2);
        int row_hi = row_lo + 8;
        if (SHIFTED) {
            int ll = lab[row_lo], lh = lab[row_hi];
            #pragma unroll
            for (int j = 0; j < 8; j++) {
                int c0 = j*8 + 2*(lane & 3);
                int lc0 = lab[c0], lc1 = lab[c0+1];
                if (lc0 != ll) sAcc[j][0] = -1e30f;
                if (lc1 != ll) sAcc[j][1] = -1e30f;
                if (lc0 != lh) sAcc[j][2] = -1e30f;
                if (lc1 != lh) sAcc[j][3] = -1e30f;
            }
        }
        float mlo = -1e30f, mhi = -1e30f;
        #pragma unroll
        for (int j = 0; j < 8; j++) {
            mlo = fmaxf(mlo, fmaxf(sAcc[j][0], sAcc[j][1]));
            mhi = fmaxf(mhi, fmaxf(sAcc[j][2], sAcc[j][3]));
        }
        mlo = fmaxf(mlo, __shfl_xor_sync(0xffffffffu, mlo, 1));
        mlo = fmaxf(mlo, __shfl_xor_sync(0xffffffffu, mlo, 2));
        mhi = fmaxf(mhi, __shfl_xor_sync(0xffffffffu, mhi, 1));
        mhi = fmaxf(mhi, __shfl_xor_sync(0xffffffffu, mhi, 2));
        float slo = 0.f, shi = 0.f;
        uint32_t pf[8][2];
        #pragma unroll
        for (int j = 0; j < 8; j++) {
            float e0 = __expf((sAcc[j][0] - mlo) * QKSCALE);
            float e1 = __expf((sAcc[j][1] - mlo) * QKSCALE);
            float e2 = __expf((sAcc[j][2] - mhi) * QKSCALE);
            float e3 = __expf((sAcc[j][3] - mhi) * QKSCALE);
            slo += e0 + e1; shi += e2 + e3;
            pf[j][0] = h2pack(e0, e1);
            pf[j][1] = h2pack(e2, e3);
        }
        slo += __shfl_xor_sync(0xffffffffu, slo, 1);
        slo += __shfl_xor_sync(0xffffffffu, slo, 2);
        shi += __shfl_xor_sync(0xffffffffu, shi, 1);
        shi += __shfl_xor_sync(0xffffffffu, shi, 2);
        float ilo = 1.f / slo, ihi = 1.f / shi;

        float oAcc[4][4];
        #pragma unroll
        for (int j = 0; j < 4; j++)
            #pragma unroll
            for (int q = 0; q < 4; q++) oAcc[j][q] = 0.f;
        #pragma unroll
        for (int t = 0; t < 4; t++) {
            uint32_t a[4] = { pf[2*t][0], pf[2*t][1], pf[2*t+1][0], pf[2*t+1][1] };
            #pragma unroll
            for (int n16 = 0; n16 < 2; n16++) {
                uint32_t b[4];
                LDSM4T(b, sbase + ((t*16 + v_row) * AT_STRIDE + vbase + n16*16 + v_colh) * 2);
                MMA16816(oAcc[2*n16],   a, b[0], b[1]);
                MMA16816(oAcc[2*n16+1], a, b[2], b[3]);
            }
        }

        __half* orow_lo = &out[(size_t)(wi*64 + row_lo) * CC + h*32];
        __half* orow_hi = &out[(size_t)(wi*64 + row_hi) * CC + h*32];
        #pragma unroll
        for (int j = 0; j < 4; j++) {
            int col = j*8 + 2*(lane & 3);
            *(__half2*)&orow_lo[col] = __floats2half2_rn(oAcc[j][0]*ilo, oAcc[j][1]*ilo);
            *(__half2*)&orow_hi[col] = __floats2half2_rn(oAcc[j][2]*ihi, oAcc[j][3]*ihi);
        }
    }
}

// ---------------- patch-merge gather + LN(512), half out --------------------
__global__ __launch_bounds__(128) void pm_ln_kernel(
    const float* __restrict__ x, const float* __restrict__ gam,
    const float* __restrict__ bet, __half* __restrict__ out)
{
    int lane = threadIdx.x & 31;
    int warp = threadIdx.x >> 5;
    int i = blockIdx.x * 4 + warp;
    int b = i / 2304, pos = i % 2304;
    int oh = pos / 48, ow = pos % 48;
    int base = b * LL;
    int src[4];
    src[0] = base + (2*oh    ) * WW + 2*ow;
    src[1] = base + (2*oh + 1) * WW + 2*ow;
    src[2] = base + (2*oh    ) * WW + 2*ow + 1;
    src[3] = base + (2*oh + 1) * WW + 2*ow + 1;
    float4 v[4];
    float s1 = 0.f, s2 = 0.f;
    #pragma unroll
    for (int k = 0; k < 4; k++) {
        v[k] = *(const float4*)&x[(size_t)src[k] * CC + lane * 4];
        s1 += v[k].x + v[k].y + v[k].z + v[k].w;
        s2 += v[k].x*v[k].x + v[k].y*v[k].y + v[k].z*v[k].z + v[k].w*v[k].w;
    }
    #pragma unroll
    for (int o = 16; o; o >>= 1) {
        s1 += __shfl_xor_sync(0xffffffffu, s1, o);
        s2 += __shfl_xor_sync(0xffffffffu, s2, o);
    }
    float mean = s1 * (1.f / 512.f);
    float var  = s2 * (1.f / 512.f) - mean * mean;
    float rstd = rsqrtf(var + 1e-5f);
    #pragma unroll
    for (int k = 0; k < 4; k++) {
        int col = k * CC + lane * 4;
        float4 g4 = *(const float4*)&gam[col];
        float4 b4 = *(const float4*)&bet[col];
        float4 o4;
        o4.x = (v[k].x - mean) * rstd * g4.x + b4.x;
        o4.y = (v[k].y - mean) * rstd * g4.y + b4.y;
        o4.z = (v[k].z - mean) * rstd * g4.z + b4.z;
        o4.w = (v[k].w - mean) * rstd * g4.w + b4.w;
        *(uint2*)&out[(size_t)i * 512 + col] = f4_to_h4(o4);
    }
}

// ---------------- host orchestration ----------------------------------------
extern "C" void kernel_launch(void* const* d_in, const int* in_sizes, int n_in,
                              void* d_out, int out_size)
{
    (void)in_sizes; (void)n_in; (void)out_size;
    const float* x = (const float*)d_in[0];
    const float* pa[12];
    const float* pb[12];
    for (int i = 0; i < 12; i++) pa[i] = (const float*)d_in[1 + i];
    for (int i = 0; i < 12; i++) pb[i] = (const float*)d_in[13 + i];
    const float* mln_g = (const float*)d_in[25];
    const float* mln_b = (const float*)d_in[26];
    const float* red_w = (const float*)d_in[27];
    float* out = (float*)d_out;

    __half *xw, *qkv, *att, *wt;
    float *xa, *xb;
    cudaGetSymbolAddress((void**)&xw,  g_xw);
    cudaGetSymbolAddress((void**)&qkv, g_qkv);
    cudaGetSymbolAddress((void**)&att, g_att);
    cudaGetSymbolAddress((void**)&xa,  g_xa);
    cudaGetSymbolAddress((void**)&xb,  g_xb);
    cudaGetSymbolAddress((void**)&wt,  g_wt);

    static bool attr_done = false;
    if (!attr_done) {
        cudaFuncSetAttribute(attn_mma<false>, cudaFuncAttributeMaxDynamicSharedMemorySize, AT_SMEM);
        cudaFuncSetAttribute(attn_mma<true>,  cudaFuncAttributeMaxDynamicSharedMemorySize, AT_SMEM);
        cudaFuncSetAttribute(gemm_wide<0>, cudaFuncAttributeMaxDynamicSharedMemorySize, GW_SMEM);
        cudaFuncSetAttribute(gemm_mlp<1>, cudaFuncAttributeMaxDynamicSharedMemorySize, MLP_SMEM);
        cudaFuncSetAttribute(gemm_mlp<2>, cudaFuncAttributeMaxDynamicSharedMemorySize, MLP_SMEM);
        attr_done = true;
    }

    __half* a_qkv_t  = wt;
    __half* a_proj_t = wt + 49152;
    __half* a_fc1_t  = wt + 65536;
    __half* a_fc2_t  = wt + 131072;
    __half* b_qkv_t  = wt + 196608;
    __half* b_proj_t = wt + 245760;
    __half* b_fc1_t  = wt + 262144;
    __half* b_fc2_t  = wt + 327680;
    __half* red_t    = wt + 393216;

    TPJobs jb;
    jb.src[0] = pa[2];  jb.dst[0] = a_qkv_t;  jb.K[0] = 128; jb.N[0] = 384;
    jb.src[1] = pa[4];  jb.dst[1] = a_proj_t; jb.K[1] = 128; jb.N[1] = 128;
    jb.src[2] = pa[8];  jb.dst[2] = a_fc1_t;  jb.K[2] = 128; jb.N[2] = 512;
    jb.src[3] = pa[10]; jb.dst[3] = a_fc2_t;  jb.K[3] = 512; jb.N[3] = 128;
    jb.src[4] = pb[2];  jb.dst[4] = b_qkv_t;  jb.K[4] = 128; jb.N[4] = 384;
    jb.src[5] = pb[4];  jb.dst[5] = b_proj_t; jb.K[5] = 128; jb.N[5] = 128;
    jb.src[6] = pb[8];  jb.dst[6] = b_fc1_t;  jb.K[6] = 128; jb.N[6] = 512;
    jb.src[7] = pb[10]; jb.dst[7] = b_fc2_t;  jb.K[7] = 512; jb.N[7] = 128;
    jb.src[8] = red_w;  jb.dst[8] = red_t;    jb.K[8] = 512; jb.N[8] = 256;
    transpose_all<<<dim3(16, 16, 9), 256>>>(jb);

    // ---------------- block a (shift 0) ----------------
    ln_kernel<true><<<ROWS/4, 128>>>(x, pa[0], pa[1], xw, 0);
    gemm_wide<0><<<ROWS/128, 256, GW_SMEM>>>(xw, a_qkv_t, pa[3], qkv, 384, 3);
    attn_mma<false><<<ROWS/NTOK, 128, AT_SMEM>>>(qkv, att);
    gemm_ln<<<ROWS/128, 256, GM_SMEM>>>(att, a_proj_t, pa[5], xa, x, pa[6], pa[7], xw, CC, 0);
    // fused fc1+GELU+fc2 + residual + LN1b(gather shift4) -> att (NOT xw: A aliases!)
    gemm_mlp<1><<<ROWS/128, 256, MLP_SMEM>>>(xw, a_fc1_t, a_fc2_t, pa[9], pa[11],
                                             xa, xa, pb[0], pb[1], att);

    // ---------------- block b (shift 4) ----------------
    gemm_wide<0><<<ROWS/128, 256, GW_SMEM>>>(att, b_qkv_t, pb[3], qkv, 384, 3);
    attn_mma<true><<<ROWS/NTOK, 128, AT_SMEM>>>(qkv, att);
    gemm_ln<<<ROWS/128, 256, GM_SMEM>>>(att, b_proj_t, pb[5], xb, xa, pb[6], pb[7], xw, CC, 4);
    gemm_mlp<2><<<ROWS/128, 256, MLP_SMEM>>>(xw, b_fc1_t, b_fc2_t, pb[9], pb[11],
                                             xb, xb, nullptr, nullptr, nullptr);

    // ---------------- patch merge ----------------
    pm_ln_kernel<<<(ROWS/4)/NTOK * 16, 128>>>(xb, mln_g, mln_b, att);
    gemm_mma<4,float><<<dim3((ROWS/4)/128, 2), 256, GM_SMEM>>>(att, red_t, nullptr, out, nullptr,
                                                               ROWS/4, 256, 512, 0);
}

// round 15
// speedup vs baseline: 1.4317x; 1.4317x over previous
#include <cuda_runtime.h>
#include <cuda_fp16.h>
#include <cstdint>

// Problem constants
#define BATCH 8
#define HH 96
#define WW 96
#define CC 128
#define LL (HH*WW)            // 9216
#define ROWS (BATCH*LL)       // 73728
#define NWIN 144
#define WS 8
#define NTOK 64
#define HEADS 4
#define HD 32
#define QKSCALE 0.17677669529663687f

// ---------------- scratch -----------------
__device__ __half g_xw [ (size_t)ROWS*CC ];
__device__ __half g_qkv[ (size_t)ROWS*3*CC ];
__device__ __half g_att[ (size_t)ROWS*CC ];
__device__ float  g_xa [ (size_t)ROWS*CC ];
__device__ float  g_xb [ (size_t)ROWS*CC ];
__device__ __half g_h  [ (size_t)ROWS*4*CC ];
__device__ __half g_wt [ 524288 ];

__device__ __forceinline__ uint32_t smem_u32(const void* p) {
    uint32_t a;
    asm("{ .reg .u64 t; cvta.to.shared.u64 t, %1; cvt.u32.u64 %0, t; }" : "=r"(a) : "l"(p));
    return a;
}
__device__ __forceinline__ float gelu_exact(float x) {
    return 0.5f * x * (1.f + erff(x * 0.70710678118654752f));
}
__device__ __forceinline__ uint2 f4_to_h4(float4 v) {
    union { uint2 u; __half2 h[2]; } cv;
    cv.h[0] = __floats2half2_rn(v.x, v.y);
    cv.h[1] = __floats2half2_rn(v.z, v.w);
    return cv.u;
}
__device__ __forceinline__ uint32_t h2pack(float a, float b) {
    union { uint32_t u; __half2 h; } cv;
    cv.h = __floats2half2_rn(a, b);
    return cv.u;
}

#define LDSM4(r, addr) \
    asm volatile("ldmatrix.sync.aligned.m8n8.x4.shared.b16 {%0,%1,%2,%3},[%4];" \
        : "=r"((r)[0]), "=r"((r)[1]), "=r"((r)[2]), "=r"((r)[3]) : "r"(addr))
#define LDSM4T(r, addr) \
    asm volatile("ldmatrix.sync.aligned.m8n8.x4.trans.shared.b16 {%0,%1,%2,%3},[%4];" \
        : "=r"((r)[0]), "=r"((r)[1]), "=r"((r)[2]), "=r"((r)[3]) : "r"(addr))
#define MMA16816(acc, a, b0, b1) \
    asm volatile("mma.sync.aligned.m16n8k16.row.col.f32.f16.f16.f32 " \
        "{%0,%1,%2,%3},{%4,%5,%6,%7},{%8,%9},{%0,%1,%2,%3};" \
        : "+f"((acc)[0]), "+f"((acc)[1]), "+f"((acc)[2]), "+f"((acc)[3]) \
        : "r"((a)[0]), "r"((a)[1]), "r"((a)[2]), "r"((a)[3]), "r"(b0), "r"(b1))

// ---------------- LayerNorm gather (block-a entry only) ----------------------
template<bool GATHER>
__global__ __launch_bounds__(128) void ln_kernel(
    const float* __restrict__ x, const float* __restrict__ gam,
    const float* __restrict__ bet, __half* __restrict__ out, int shift)
{
    int lane = threadIdx.x & 31;
    int warp = threadIdx.x >> 5;
    int r = blockIdx.x * 4 + warp;
    const float* src;
    if (GATHER) {
        int wi = r >> 6, n = r & 63;
        int b  = wi / NWIN, wl = wi % NWIN;
        int whi = wl / 12, wwi = wl % 12;
        int h0 = whi * 8 + (n >> 3), w0 = wwi * 8 + (n & 7);
        int hs = h0 + shift; if (hs >= HH) hs -= HH;
        int ws_ = w0 + shift; if (ws_ >= WW) ws_ -= WW;
        src = &x[(size_t)(b * LL + hs * WW + ws_) * CC];
    } else {
        src = &x[(size_t)r * CC];
    }
    float4 v = *(const float4*)&src[lane * 4];
    float s1 = v.x + v.y + v.z + v.w;
    float s2 = v.x*v.x + v.y*v.y + v.z*v.z + v.w*v.w;
    #pragma unroll
    for (int o = 16; o; o >>= 1) {
        s1 += __shfl_xor_sync(0xffffffffu, s1, o);
        s2 += __shfl_xor_sync(0xffffffffu, s2, o);
    }
    float mean = s1 * (1.f / CC);
    float var  = s2 * (1.f / CC) - mean * mean;
    float rstd = rsqrtf(var + 1e-5f);
    float4 g4 = *(const float4*)&gam[lane * 4];
    float4 b4 = *(const float4*)&bet[lane * 4];
    float4 o4;
    o4.x = (v.x - mean) * rstd * g4.x + b4.x;
    o4.y = (v.y - mean) * rstd * g4.y + b4.y;
    o4.z = (v.z - mean) * rstd * g4.z + b4.z;
    o4.w = (v.w - mean) * rstd * g4.w + b4.w;
    *(uint2*)&out[(size_t)r * CC + lane * 4] = f4_to_h4(o4);
}

// ---------------- batched weight transpose ----------------------------------
struct TPJobs {
    const float* src[9];
    __half* dst[9];
    int K[9];
    int N[9];
};
__global__ __launch_bounds__(256) void transpose_all(TPJobs jb)
{
    __shared__ float t[32][33];
    int m = blockIdx.z;
    int K = jb.K[m], N = jb.N[m];
    int k0 = blockIdx.x * 32, n0 = blockIdx.y * 32;
    if (k0 >= K || n0 >= N) return;
    const float* src = jb.src[m];
    __half* dst = jb.dst[m];
    int x = threadIdx.x & 31, y = threadIdx.x >> 5;
    #pragma unroll
    for (int i = 0; i < 32; i += 8)
        t[y + i][x] = src[(size_t)(k0 + y + i) * N + n0 + x];
    __syncthreads();
    #pragma unroll
    for (int i = 0; i < 32; i += 8)
        dst[(size_t)(n0 + y + i) * K + k0 + x] = __float2half_rn(t[x][y + i]);
}

// ---------------- shared GEMM plumbing (k32-chunk path) ----------------------
#define AS_STRIDE 40
#define TILE_H   (128*AS_STRIDE)
#define GM_SMEM  (4*TILE_H*2)              // 40960 bytes

__device__ __forceinline__ void copy_chunk(
    const __half* __restrict__ A, const __half* __restrict__ B,
    int bm, int bn, int K, int k0, __half* sA, __half* sB, int tid)
{
    uint32_t a_s = smem_u32(sA), b_s = smem_u32(sB);
    #pragma unroll
    for (int i = 0; i < 2; i++) {
        int idx = tid + i * 256;
        int row = idx >> 2, q = idx & 3;
        const __half* ga = &A[(size_t)(bm + row) * K + k0 + q * 8];
        const __half* gb = &B[(size_t)(bn + row) * K + k0 + q * 8];
        uint32_t so = (row * AS_STRIDE + q * 8) * 2;
        asm volatile("cp.async.cg.shared.global [%0],[%1],16;" :: "r"(a_s + so), "l"(ga));
        asm volatile("cp.async.cg.shared.global [%0],[%1],16;" :: "r"(b_s + so), "l"(gb));
    }
    asm volatile("cp.async.commit_group;" ::: "memory");
}

// ---------------- general GEMM (EPI 0:+bias | 2:+bias,GELU | 4:plain) --------
template<int EPI, typename OT>
__global__ __launch_bounds__(256)
void gemm_mma(const __half* __restrict__ A, const __half* __restrict__ B,
              const float* __restrict__ bias, OT* __restrict__ C,
              const float* __restrict__ res, int M, int N, int K, int shift)
{
    extern __shared__ __half smh[];
    __half* bufA[2] = { smh,          smh + 2*TILE_H };
    __half* bufB[2] = { smh + TILE_H, smh + 3*TILE_H };
    int tid = threadIdx.x, lane = tid & 31, wid = tid >> 5;
    int g = lane >> 2, kq = lane & 3;
    int warpM = wid & 3, warpN = wid >> 2;
    int bm = blockIdx.x * 128, bn = blockIdx.y * 128;

    float acc[2][8][4];
    #pragma unroll
    for (int i = 0; i < 2; i++)
        #pragma unroll
        for (int j = 0; j < 8; j++)
            #pragma unroll
            for (int q = 0; q < 4; q++) acc[i][j][q] = 0.f;

    int nc = K >> 5;
    copy_chunk(A, B, bm, bn, K, 0, bufA[0], bufB[0], tid);

    uint32_t a_off = (((warpM * 32 + (lane & 15)) * AS_STRIDE) + ((lane >> 4) << 3)) * 2;
    uint32_t b_off = (((warpN * 64 + (lane & 7) + (((lane >> 4) & 1) << 3)) * AS_STRIDE)
                     + (((lane >> 3) & 1) << 3)) * 2;

    for (int c = 0; c < nc; c++) {
        if (c + 1 < nc) {
            copy_chunk(A, B, bm, bn, K, (c + 1) << 5, bufA[(c+1)&1], bufB[(c+1)&1], tid);
            asm volatile("cp.async.wait_group 1;" ::: "memory");
        } else {
            asm volatile("cp.async.wait_group 0;" ::: "memory");
        }
        __syncthreads();

        uint32_t ab = smem_u32(bufA[c&1]) + a_off;
        uint32_t bb = smem_u32(bufB[c&1]) + b_off;
        #pragma unroll
        for (int ks = 0; ks < 2; ks++) {
            uint32_t a[2][4], b[4][4];
            LDSM4(a[0], ab + ks * 32);
            LDSM4(a[1], ab + 16 * AS_STRIDE * 2 + ks * 32);
            #pragma unroll
            for (int j16 = 0; j16 < 4; j16++)
                LDSM4(b[j16], bb + j16 * 16 * AS_STRIDE * 2 + ks * 32);
            #pragma unroll
            for (int i = 0; i < 2; i++)
                #pragma unroll
                for (int j = 0; j < 8; j++) {
                    uint32_t b0 = b[j >> 1][(j & 1) * 2];
                    uint32_t b1 = b[j >> 1][(j & 1) * 2 + 1];
                    MMA16816(acc[i][j], a[i], b0, b1);
                }
        }
        __syncthreads();
    }

    #pragma unroll
    for (int i = 0; i < 2; i++) {
        #pragma unroll
        for (int rr = 0; rr < 2; rr++) {
            int gr = bm + warpM * 32 + i * 16 + g + rr * 8;
            #pragma unroll
            for (int j = 0; j < 8; j++) {
                int col = bn + warpN * 64 + j * 8 + 2 * kq;
                float vx = acc[i][j][rr*2+0];
                float vy = acc[i][j][rr*2+1];
                if (EPI != 4) {
                    vx += __ldg(&bias[col]);
                    vy += __ldg(&bias[col+1]);
                }
                if (EPI == 2) { vx = gelu_exact(vx); vy = gelu_exact(vy); }
                if (sizeof(OT) == 2) {
                    *(__half2*)&((__half*)C)[(size_t)gr * N + col] = __floats2half2_rn(vx, vy);
                } else {
                    *(float2*)&((float*)C)[(size_t)gr * N + col] = make_float2(vx, vy);
                }
            }
        }
    }
}

// ---------------- wide GEMM: K=128, A resident full-K, loop over N-tiles -----
#define AW_STRIDE 136                       // 128 k-halves + 8 pad
#define AW_TILE   (128*AW_STRIDE)           // halves (17408)
#define GW_SMEM   (3*AW_TILE*2)             // A + 2 B buffers = 104448 bytes

template<int EPI>
__global__ __launch_bounds__(256)
void gemm_wide(const __half* __restrict__ A, const __half* __restrict__ B,
               const float* __restrict__ bias, __half* __restrict__ C,
               int N, int nt)
{
    extern __shared__ __half smh[];
    __half* sA = smh;
    __half* sB[2] = { smh + AW_TILE, smh + 2*AW_TILE };
    int tid = threadIdx.x, lane = tid & 31, wid = tid >> 5;
    int g = lane >> 2, kq = lane & 3;
    int warpM = wid & 3, warpN = wid >> 2;
    int bm = blockIdx.x * 128;

    {
        uint32_t a_s = smem_u32(sA), b_s = smem_u32(sB[0]);
        #pragma unroll
        for (int i = 0; i < 8; i++) {
            int idx = tid + i * 256;
            int row = idx >> 4, q = idx & 15;
            uint32_t so = (row * AW_STRIDE + q * 8) * 2;
            asm volatile("cp.async.cg.shared.global [%0],[%1],16;"
                :: "r"(a_s + so), "l"(&A[(size_t)(bm + row) * 128 + q * 8]));
            asm volatile("cp.async.cg.shared.global [%0],[%1],16;"
                :: "r"(b_s + so), "l"(&B[(size_t)row * 128 + q * 8]));
        }
        asm volatile("cp.async.commit_group;" ::: "memory");
        if (nt > 1) {
            uint32_t b1_s = smem_u32(sB[1]);
            #pragma unroll
            for (int i = 0; i < 8; i++) {
                int idx = tid + i * 256;
                int row = idx >> 4, q = idx & 15;
                uint32_t so = (row * AW_STRIDE + q * 8) * 2;
                asm volatile("cp.async.cg.shared.global [%0],[%1],16;"
                    :: "r"(b1_s + so), "l"(&B[(size_t)(128 + row) * 128 + q * 8]));
            }
            asm volatile("cp.async.commit_group;" ::: "memory");
        }
    }

    uint32_t a_off = (((warpM * 32 + (lane & 15)) * AW_STRIDE) + ((lane >> 4) << 3)) * 2;
    uint32_t b_off = (((warpN * 64 + (lane & 7) + (((lane >> 4) & 1) << 3)) * AW_STRIDE)
                     + (((lane >> 3) & 1) << 3)) * 2;
    uint32_t ab = smem_u32(sA) + a_off;

    for (int bn = 0; bn < nt; bn++) {
        if (bn + 1 < nt)
            asm volatile("cp.async.wait_group 1;" ::: "memory");
        else
            asm volatile("cp.async.wait_group 0;" ::: "memory");
        __syncthreads();

        float acc[2][8][4];
        #pragma unroll
        for (int i = 0; i < 2; i++)
            #pragma unroll
            for (int j = 0; j < 8; j++)
                #pragma unroll
                for (int q = 0; q < 4; q++) acc[i][j][q] = 0.f;

        uint32_t bb = smem_u32(sB[bn & 1]) + b_off;
        #pragma unroll
        for (int ks = 0; ks < 8; ks++) {
            uint32_t a[2][4], b[4][4];
            LDSM4(a[0], ab + ks * 32);
            LDSM4(a[1], ab + 16 * AW_STRIDE * 2 + ks * 32);
            #pragma unroll
            for (int j16 = 0; j16 < 4; j16++)
                LDSM4(b[j16], bb + j16 * 16 * AW_STRIDE * 2 + ks * 32);
            #pragma unroll
            for (int i = 0; i < 2; i++)
                #pragma unroll
                for (int j = 0; j < 8; j++) {
                    uint32_t b0 = b[j >> 1][(j & 1) * 2];
                    uint32_t b1 = b[j >> 1][(j & 1) * 2 + 1];
                    MMA16816(acc[i][j], a[i], b0, b1);
                }
        }

        #pragma unroll
        for (int i = 0; i < 2; i++) {
            #pragma unroll
            for (int rr = 0; rr < 2; rr++) {
                int gr = bm + warpM * 32 + i * 16 + g + rr * 8;
                #pragma unroll
                for (int j = 0; j < 8; j++) {
                    int col = bn * 128 + warpN * 64 + j * 8 + 2 * kq;
                    float vx = acc[i][j][rr*2+0] + __ldg(&bias[col]);
                    float vy = acc[i][j][rr*2+1] + __ldg(&bias[col+1]);
                    if (EPI == 2) { vx = gelu_exact(vx); vy = gelu_exact(vy); }
                    *(__half2*)&C[(size_t)gr * N + col] = __floats2half2_rn(vx, vy);
                }
            }
        }

        if (bn + 2 < nt) {
            __syncthreads();
            uint32_t bs = smem_u32(sB[bn & 1]);
            #pragma unroll
            for (int i = 0; i < 8; i++) {
                int idx = tid + i * 256;
                int row = idx >> 4, q = idx & 15;
                uint32_t so = (row * AW_STRIDE + q * 8) * 2;
                asm volatile("cp.async.cg.shared.global [%0],[%1],16;"
                    :: "r"(bs + so), "l"(&B[(size_t)((bn + 2) * 128 + row) * 128 + q * 8]));
            }
            asm volatile("cp.async.commit_group;" ::: "memory");
        } else {
            __syncthreads();
        }
    }
}

// ---------------- N=128 GEMM with fused residual + LayerNorm -----------------
// MODE 0: proj (scatter+shift, LN->lnout spatial)
// MODE 1: fc2a (LN->lnout window-gather shift4)
// MODE 2: fc2b (no LN)
template<int MODE>
__global__ __launch_bounds__(256)
void gemm_ln(const __half* __restrict__ A, const __half* __restrict__ B,
             const float* __restrict__ bias, float* __restrict__ C,
             const float* __restrict__ res, const float* __restrict__ gam,
             const float* __restrict__ bet, __half* __restrict__ lnout,
             int K, int shift)
{
    extern __shared__ __half smh[];
    __half* bufA[2] = { smh,          smh + 2*TILE_H };
    __half* bufB[2] = { smh + TILE_H, smh + 3*TILE_H };
    int tid = threadIdx.x, lane = tid & 31, wid = tid >> 5;
    int g = lane >> 2, kq = lane & 3;
    int bm = blockIdx.x * 128;

    float acc[16][4];
    #pragma unroll
    for (int j = 0; j < 16; j++)
        #pragma unroll
        for (int q = 0; q < 4; q++) acc[j][q] = 0.f;

    int nc = K >> 5;
    copy_chunk(A, B, bm, 0, K, 0, bufA[0], bufB[0], tid);

    uint32_t a_off = (((wid * 16 + (lane & 15)) * AS_STRIDE) + ((lane >> 4) << 3)) * 2;
    uint32_t b_off = ((((lane & 7) + (((lane >> 4) & 1) << 3)) * AS_STRIDE)
                     + (((lane >> 3) & 1) << 3)) * 2;

    for (int c = 0; c < nc; c++) {
        if (c + 1 < nc) {
            copy_chunk(A, B, bm, 0, K, (c + 1) << 5, bufA[(c+1)&1], bufB[(c+1)&1], tid);
            asm volatile("cp.async.wait_group 1;" ::: "memory");
        } else {
            asm volatile("cp.async.wait_group 0;" ::: "memory");
        }
        __syncthreads();

        uint32_t ab = smem_u32(bufA[c&1]) + a_off;
        uint32_t bb = smem_u32(bufB[c&1]) + b_off;
        #pragma unroll
        for (int ks = 0; ks < 2; ks++) {
            uint32_t a[4];
            LDSM4(a, ab + ks * 32);
            #pragma unroll
            for (int j16 = 0; j16 < 8; j16++) {
                uint32_t b[4];
                LDSM4(b, bb + j16 * 16 * AS_STRIDE * 2 + ks * 32);
                MMA16816(acc[2*j16],   a, b[0], b[1]);
                MMA16816(acc[2*j16+1], a, b[2], b[3]);
            }
        }
        __syncthreads();
    }

    int r0 = bm + wid * 16 + g;
    int r1 = r0 + 8;
    int dst0, dst1;
    if (MODE == 0) {
        int d[2];
        #pragma unroll
        for (int rr = 0; rr < 2; rr++) {
            int gr = rr ? r1 : r0;
            int wi = gr >> 6, n = gr & 63;
            int b  = wi / NWIN, wl = wi % NWIN;
            int whi = wl / 12, wwi = wl % 12;
            int h0 = whi * 8 + (n >> 3), w0 = wwi * 8 + (n & 7);
            int h = h0 + shift; if (h >= HH) h -= HH;
            int w = w0 + shift; if (w >= WW) w -= WW;
            d[rr] = b * LL + h * WW + w;
        }
        dst0 = d[0]; dst1 = d[1];
    } else {
        dst0 = r0; dst1 = r1;
    }

    float vv[16][4];
    float s1a = 0.f, s2a = 0.f, s1b = 0.f, s2b = 0.f;
    #pragma unroll
    for (int j = 0; j < 16; j++) {
        int col = j * 8 + 2 * kq;
        float bx = __ldg(&bias[col]), by = __ldg(&bias[col+1]);
        float2 ra = *(const float2*)&res[(size_t)dst0 * CC + col];
        float2 rb = *(const float2*)&res[(size_t)dst1 * CC + col];
        float v0 = acc[j][0] + bx + ra.x;
        float v1 = acc[j][1] + by + ra.y;
        float v2 = acc[j][2] + bx + rb.x;
        float v3 = acc[j][3] + by + rb.y;
        vv[j][0] = v0; vv[j][1] = v1; vv[j][2] = v2; vv[j][3] = v3;
        *(float2*)&C[(size_t)dst0 * CC + col] = make_float2(v0, v1);
        *(float2*)&C[(size_t)dst1 * CC + col] = make_float2(v2, v3);
        if (MODE != 2) {
            s1a += v0 + v1; s2a += v0*v0 + v1*v1;
            s1b += v2 + v3; s2b += v2*v2 + v3*v3;
        }
    }
    if (MODE == 2) return;

    s1a += __shfl_xor_sync(0xffffffffu, s1a, 1);
    s1a += __shfl_xor_sync(0xffffffffu, s1a, 2);
    s2a += __shfl_xor_sync(0xffffffffu, s2a, 1);
    s2a += __shfl_xor_sync(0xffffffffu, s2a, 2);
    s1b += __shfl_xor_sync(0xffffffffu, s1b, 1);
    s1b += __shfl_xor_sync(0xffffffffu, s1b, 2);
    s2b += __shfl_xor_sync(0xffffffffu, s2b, 1);
    s2b += __shfl_xor_sync(0xffffffffu, s2b, 2);

    float ma = s1a * (1.f/CC), va = s2a * (1.f/CC) - ma*ma;
    float mb = s1b * (1.f/CC), vb = s2b * (1.f/CC) - mb*mb;
    float ra_ = rsqrtf(va + 1e-5f), rb_ = rsqrtf(vb + 1e-5f);

    int ln0, ln1;
    if (MODE == 0) { ln0 = dst0; ln1 = dst1; }
    else {
        int d[2];
        #pragma unroll
        for (int rr = 0; rr < 2; rr++) {
            int gr = rr ? r1 : r0;
            int b = gr / LL, rem = gr % LL;
            int h = rem / WW, w = rem % WW;
            int h0 = h - 4; if (h0 < 0) h0 += HH;
            int w0 = w - 4; if (w0 < 0) w0 += WW;
            d[rr] = b * LL + ((h0 >> 3) * 12 + (w0 >> 3)) * 64 + (h0 & 7) * 8 + (w0 & 7);
        }
        ln0 = d[0]; ln1 = d[1];
    }

    #pragma unroll
    for (int j = 0; j < 16; j++) {
        int col = j * 8 + 2 * kq;
        float gx = __ldg(&gam[col]), gy = __ldg(&gam[col+1]);
        float bx = __ldg(&bet[col]), by = __ldg(&bet[col+1]);
        *(__half2*)&lnout[(size_t)ln0 * CC + col] =
            __floats2half2_rn((vv[j][0]-ma)*ra_*gx+bx, (vv[j][1]-ma)*ra_*gy+by);
        *(__half2*)&lnout[(size_t)ln1 * CC + col] =
            __floats2half2_rn((vv[j][2]-mb)*rb_*gx+bx, (vv[j][3]-mb)*rb_*gy+by);
    }
}

// ---------------- MMA windowed attention (conflict-free stride 392) ----------
#define AT_STRIDE 392
#define AT_SMEM   (64*AT_STRIDE*2 + 64*4)   // 50432 bytes

template<bool SHIFTED>
__global__ __launch_bounds__(128) void attn_mma(
    const __half* __restrict__ qkv, __half* __restrict__ out)
{
    extern __shared__ __half smw[];
    int* lab = (int*)(smw + 64*AT_STRIDE);
    int tid = threadIdx.x, lane = tid & 31, h = tid >> 5;
    int wi = blockIdx.x;

    const uint4* gsrc = (const uint4*)(qkv + (size_t)wi * 64 * 384);
    #pragma unroll
    for (int i = 0; i < 24; i++) {
        int idx = tid + i * 128;
        int row = idx / 48, seg = idx % 48;
        *(uint4*)&smw[row * AT_STRIDE + seg * 8] = gsrc[row * 48 + seg];
    }
    if (SHIFTED && tid < 64) {
        int wl = wi % NWIN;
        int whi = wl / 12, wwi = wl % 12;
        int hh = whi * 8 + (tid >> 3), ww_ = wwi * 8 + (tid & 7);
        int hr = (hh < HH - WS) ? 0 : ((hh < HH - 4) ? 1 : 2);
        int wr = (ww_ < WW - WS) ? 0 : ((ww_ < WW - 4) ? 1 : 2);
        lab[tid] = hr * 3 + wr;
    }
    __syncthreads();

    uint32_t sbase = smem_u32(smw);
    int qbase = h * 32;
    int kbase = 128 + h * 32;
    int vbase = 256 + h * 32;

    uint32_t q_row  = lane & 15;
    uint32_t q_colh = (lane >> 4) << 3;
    uint32_t k_row  = (lane & 7) + (((lane >> 4) & 1) << 3);
    uint32_t k_colh = ((lane >> 3) & 1) << 3;
    uint32_t v_row  = lane & 15;
    uint32_t v_colh = (lane >> 4) << 3;

    #pragma unroll
    for (int mt = 0; mt < 4; mt++) {
        float sAcc[8][4];
        #pragma unroll
        for (int j = 0; j < 8; j++)
            #pragma unroll
            for (int q = 0; q < 4; q++) sAcc[j][q] = 0.f;
        #pragma unroll
        for (int kt = 0; kt < 2; kt++) {
            uint32_t a[4];
            LDSM4(a, sbase + ((mt*16 + q_row) * AT_STRIDE + qbase + q_colh + kt*16) * 2);
            #pragma unroll
            for (int j16 = 0; j16 < 4; j16++) {
                uint32_t b[4];
                LDSM4(b, sbase + ((j16*16 + k_row) * AT_STRIDE + kbase + k_colh + kt*16) * 2);
                MMA16816(sAcc[2*j16],   a, b[0], b[1]);
                MMA16816(sAcc[2*j16+1], a, b[2], b[3]);
            }
        }

        int row_lo = mt*16 + (lane >> 2);
        int row_hi = row_lo + 8;
        if (SHIFTED) {
            int ll = lab[row_lo], lh = lab[row_hi];
            #pragma unroll
            for (int j = 0; j < 8; j++) {
                int c0 = j*8 + 2*(lane & 3);
                int lc0 = lab[c0], lc1 = lab[c0+1];
                if (lc0 != ll) sAcc[j][0] = -1e30f;
                if (lc1 != ll) sAcc[j][1] = -1e30f;
                if (lc0 != lh) sAcc[j][2] = -1e30f;
                if (lc1 != lh) sAcc[j][3] = -1e30f;
            }
        }
        float mlo = -1e30f, mhi = -1e30f;
        #pragma unroll
        for (int j = 0; j < 8; j++) {
            mlo = fmaxf(mlo, fmaxf(sAcc[j][0], sAcc[j][1]));
            mhi = fmaxf(mhi, fmaxf(sAcc[j][2], sAcc[j][3]));
        }
        mlo = fmaxf(mlo, __shfl_xor_sync(0xffffffffu, mlo, 1));
        mlo = fmaxf(mlo, __shfl_xor_sync(0xffffffffu, mlo, 2));
        mhi = fmaxf(mhi, __shfl_xor_sync(0xffffffffu, mhi, 1));
        mhi = fmaxf(mhi, __shfl_xor_sync(0xffffffffu, mhi, 2));
        float slo = 0.f, shi = 0.f;
        uint32_t pf[8][2];
        #pragma unroll
        for (int j = 0; j < 8; j++) {
            float e0 = __expf((sAcc[j][0] - mlo) * QKSCALE);
            float e1 = __expf((sAcc[j][1] - mlo) * QKSCALE);
            float e2 = __expf((sAcc[j][2] - mhi) * QKSCALE);
            float e3 = __expf((sAcc[j][3] - mhi) * QKSCALE);
            slo += e0 + e1; shi += e2 + e3;
            pf[j][0] = h2pack(e0, e1);
            pf[j][1] = h2pack(e2, e3);
        }
        slo += __shfl_xor_sync(0xffffffffu, slo, 1);
        slo += __shfl_xor_sync(0xffffffffu, slo, 2);
        shi += __shfl_xor_sync(0xffffffffu, shi, 1);
        shi += __shfl_xor_sync(0xffffffffu, shi, 2);
        float ilo = 1.f / slo, ihi = 1.f / shi;

        float oAcc[4][4];
        #pragma unroll
        for (int j = 0; j < 4; j++)
            #pragma unroll
            for (int q = 0; q < 4; q++) oAcc[j][q] = 0.f;
        #pragma unroll
        for (int t = 0; t < 4; t++) {
            uint32_t a[4] = { pf[2*t][0], pf[2*t][1], pf[2*t+1][0], pf[2*t+1][1] };
            #pragma unroll
            for (int n16 = 0; n16 < 2; n16++) {
                uint32_t b[4];
                LDSM4T(b, sbase + ((t*16 + v_row) * AT_STRIDE + vbase + n16*16 + v_colh) * 2);
                MMA16816(oAcc[2*n16],   a, b[0], b[1]);
                MMA16816(oAcc[2*n16+1], a, b[2], b[3]);
            }
        }

        __half* orow_lo = &out[(size_t)(wi*64 + row_lo) * CC + h*32];
        __half* orow_hi = &out[(size_t)(wi*64 + row_hi) * CC + h*32];
        #pragma unroll
        for (int j = 0; j < 4; j++) {
            int col = j*8 + 2*(lane & 3);
            *(__half2*)&orow_lo[col] = __floats2half2_rn(oAcc[j][0]*ilo, oAcc[j][1]*ilo);
            *(__half2*)&orow_hi[col] = __floats2half2_rn(oAcc[j][2]*ihi, oAcc[j][3]*ihi);
        }
    }
}

// ---------------- patch-merge gather + LN(512), half out --------------------
__global__ __launch_bounds__(128) void pm_ln_kernel(
    const float* __restrict__ x, const float* __restrict__ gam,
    const float* __restrict__ bet, __half* __restrict__ out)
{
    int lane = threadIdx.x & 31;
    int warp = threadIdx.x >> 5;
    int i = blockIdx.x * 4 + warp;
    int b = i / 2304, pos = i % 2304;
    int oh = pos / 48, ow = pos % 48;
    int base = b * LL;
    int src[4];
    src[0] = base + (2*oh    ) * WW + 2*ow;
    src[1] = base + (2*oh + 1) * WW + 2*ow;
    src[2] = base + (2*oh    ) * WW + 2*ow + 1;
    src[3] = base + (2*oh + 1) * WW + 2*ow + 1;
    float4 v[4];
    float s1 = 0.f, s2 = 0.f;
    #pragma unroll
    for (int k = 0; k < 4; k++) {
        v[k] = *(const float4*)&x[(size_t)src[k] * CC + lane * 4];
        s1 += v[k].x + v[k].y + v[k].z + v[k].w;
        s2 += v[k].x*v[k].x + v[k].y*v[k].y + v[k].z*v[k].z + v[k].w*v[k].w;
    }
    #pragma unroll
    for (int o = 16; o; o >>= 1) {
        s1 += __shfl_xor_sync(0xffffffffu, s1, o);
        s2 += __shfl_xor_sync(0xffffffffu, s2, o);
    }
    float mean = s1 * (1.f / 512.f);
    float var  = s2 * (1.f / 512.f) - mean * mean;
    float rstd = rsqrtf(var + 1e-5f);
    #pragma unroll
    for (int k = 0; k < 4; k++) {
        int col = k * CC + lane * 4;
        float4 g4 = *(const float4*)&gam[col];
        float4 b4 = *(const float4*)&bet[col];
        float4 o4;
        o4.x = (v[k].x - mean) * rstd * g4.x + b4.x;
        o4.y = (v[k].y - mean) * rstd * g4.y + b4.y;
        o4.z = (v[k].z - mean) * rstd * g4.z + b4.z;
        o4.w = (v[k].w - mean) * rstd * g4.w + b4.w;
        *(uint2*)&out[(size_t)i * 512 + col] = f4_to_h4(o4);
    }
}

// ---------------- host orchestration ----------------------------------------
extern "C" void kernel_launch(void* const* d_in, const int* in_sizes, int n_in,
                              void* d_out, int out_size)
{
    (void)in_sizes; (void)n_in; (void)out_size;
    const float* x = (const float*)d_in[0];
    const float* pa[12];
    const float* pb[12];
    for (int i = 0; i < 12; i++) pa[i] = (const float*)d_in[1 + i];
    for (int i = 0; i < 12; i++) pb[i] = (const float*)d_in[13 + i];
    const float* mln_g = (const float*)d_in[25];
    const float* mln_b = (const float*)d_in[26];
    const float* red_w = (const float*)d_in[27];
    float* out = (float*)d_out;

    __half *xw, *qkv, *att, *h, *wt;
    float *xa, *xb;
    cudaGetSymbolAddress((void**)&xw,  g_xw);
    cudaGetSymbolAddress((void**)&qkv, g_qkv);
    cudaGetSymbolAddress((void**)&att, g_att);
    cudaGetSymbolAddress((void**)&xa,  g_xa);
    cudaGetSymbolAddress((void**)&xb,  g_xb);
    cudaGetSymbolAddress((void**)&h,   g_h);
    cudaGetSymbolAddress((void**)&wt,  g_wt);

    static bool attr_done = false;
    if (!attr_done) {
        cudaFuncSetAttribute(attn_mma<false>, cudaFuncAttributeMaxDynamicSharedMemorySize, AT_SMEM);
        cudaFuncSetAttribute(attn_mma<true>,  cudaFuncAttributeMaxDynamicSharedMemorySize, AT_SMEM);
        cudaFuncSetAttribute(gemm_wide<0>, cudaFuncAttributeMaxDynamicSharedMemorySize, GW_SMEM);
        cudaFuncSetAttribute(gemm_wide<2>, cudaFuncAttributeMaxDynamicSharedMemorySize, GW_SMEM);
        attr_done = true;
    }

    __half* a_qkv_t  = wt;
    __half* a_proj_t = wt + 49152;
    __half* a_fc1_t  = wt + 65536;
    __half* a_fc2_t  = wt + 131072;
    __half* b_qkv_t  = wt + 196608;
    __half* b_proj_t = wt + 245760;
    __half* b_fc1_t  = wt + 262144;
    __half* b_fc2_t  = wt + 327680;
    __half* red_t    = wt + 393216;

    TPJobs jb;
    jb.src[0] = pa[2];  jb.dst[0] = a_qkv_t;  jb.K[0] = 128; jb.N[0] = 384;
    jb.src[1] = pa[4];  jb.dst[1] = a_proj_t; jb.K[1] = 128; jb.N[1] = 128;
    jb.src[2] = pa[8];  jb.dst[2] = a_fc1_t;  jb.K[2] = 128; jb.N[2] = 512;
    jb.src[3] = pa[10]; jb.dst[3] = a_fc2_t;  jb.K[3] = 512; jb.N[3] = 128;
    jb.src[4] = pb[2];  jb.dst[4] = b_qkv_t;  jb.K[4] = 128; jb.N[4] = 384;
    jb.src[5] = pb[4];  jb.dst[5] = b_proj_t; jb.K[5] = 128; jb.N[5] = 128;
    jb.src[6] = pb[8];  jb.dst[6] = b_fc1_t;  jb.K[6] = 128; jb.N[6] = 512;
    jb.src[7] = pb[10]; jb.dst[7] = b_fc2_t;  jb.K[7] = 512; jb.N[7] = 128;
    jb.src[8] = red_w;  jb.dst[8] = red_t;    jb.K[8] = 512; jb.N[8] = 256;
    transpose_all<<<dim3(16, 16, 9), 256>>>(jb);

    // ---------------- block a (shift 0) ----------------
    ln_kernel<true><<<ROWS/4, 128>>>(x, pa[0], pa[1], xw, 0);
    gemm_wide<0><<<ROWS/128, 256, GW_SMEM>>>(xw, a_qkv_t, pa[3], qkv, 384, 3);
    attn_mma<false><<<ROWS/NTOK, 128, AT_SMEM>>>(qkv, att);
    gemm_ln<0><<<ROWS/128, 256, GM_SMEM>>>(att, a_proj_t, pa[5], xa, x, pa[6], pa[7], xw, CC, 0);
    gemm_wide<2><<<ROWS/128, 256, GW_SMEM>>>(xw, a_fc1_t, pa[9], h, 512, 4);
    gemm_ln<1><<<ROWS/128, 256, GM_SMEM>>>(h, a_fc2_t, pa[11], xa, xa, pb[0], pb[1], xw, 512, 4);

    // ---------------- block b (shift 4) ----------------
    gemm_wide<0><<<ROWS/128, 256, GW_SMEM>>>(xw, b_qkv_t, pb[3], qkv, 384, 3);
    attn_mma<true><<<ROWS/NTOK, 128, AT_SMEM>>>(qkv, att);
    gemm_ln<0><<<ROWS/128, 256, GM_SMEM>>>(att, b_proj_t, pb[5], xb, xa, pb[6], pb[7], xw, CC, 4);
    gemm_wide<2><<<ROWS/128, 256, GW_SMEM>>>(xw, b_fc1_t, pb[9], h, 512, 4);
    gemm_ln<2><<<ROWS/128, 256, GM_SMEM>>>(h, b_fc2_t, pb[11], xb, xb, nullptr, nullptr, nullptr, 512, 0);

    // ---------------- patch merge ----------------
    pm_ln_kernel<<<(ROWS/4)/NTOK * 16, 128>>>(xb, mln_g, mln_b, att);
    gemm_mma<4,float><<<dim3((ROWS/4)/128, 2), 256, GM_SMEM>>>(att, red_t, nullptr, out, nullptr,
                                                               ROWS/4, 256, 512, 0);
}

// round 16
// speedup vs baseline: 1.4330x; 1.0009x over previous
#include <cuda_runtime.h>
#include <cuda_fp16.h>
#include <cstdint>

// Problem constants
#define BATCH 8
#define HH 96
#define WW 96
#define CC 128
#define LL (HH*WW)            // 9216
#define ROWS (BATCH*LL)       // 73728
#define NWIN 144
#define WS 8
#define NTOK 64
#define HEADS 4
#define HD 32
#define QKSCALE 0.17677669529663687f

// ---------------- scratch -----------------
__device__ __half g_xw [ (size_t)ROWS*CC ];
__device__ __half g_qkv[ (size_t)ROWS*3*CC ];
__device__ __half g_att[ (size_t)ROWS*CC ];
__device__ float  g_xa [ (size_t)ROWS*CC ];
__device__ float  g_xb [ (size_t)ROWS*CC ];
__device__ __half g_h  [ (size_t)ROWS*4*CC ];
__device__ __half g_wt [ 524288 ];

__device__ __forceinline__ uint32_t smem_u32(const void* p) {
    uint32_t a;
    asm("{ .reg .u64 t; cvta.to.shared.u64 t, %1; cvt.u32.u64 %0, t; }" : "=r"(a) : "l"(p));
    return a;
}
__device__ __forceinline__ float gelu_exact(float x) {
    return 0.5f * x * (1.f + erff(x * 0.70710678118654752f));
}
__device__ __forceinline__ uint2 f4_to_h4(float4 v) {
    union { uint2 u; __half2 h[2]; } cv;
    cv.h[0] = __floats2half2_rn(v.x, v.y);
    cv.h[1] = __floats2half2_rn(v.z, v.w);
    return cv.u;
}
__device__ __forceinline__ uint32_t h2pack(float a, float b) {
    union { uint32_t u; __half2 h; } cv;
    cv.h = __floats2half2_rn(a, b);
    return cv.u;
}

#define LDSM4(r, addr) \
    asm volatile("ldmatrix.sync.aligned.m8n8.x4.shared.b16 {%0,%1,%2,%3},[%4];" \
        : "=r"((r)[0]), "=r"((r)[1]), "=r"((r)[2]), "=r"((r)[3]) : "r"(addr))
#define LDSM4T(r, addr) \
    asm volatile("ldmatrix.sync.aligned.m8n8.x4.trans.shared.b16 {%0,%1,%2,%3},[%4];" \
        : "=r"((r)[0]), "=r"((r)[1]), "=r"((r)[2]), "=r"((r)[3]) : "r"(addr))
#define MMA16816(acc, a, b0, b1) \
    asm volatile("mma.sync.aligned.m16n8k16.row.col.f32.f16.f16.f32 " \
        "{%0,%1,%2,%3},{%4,%5,%6,%7},{%8,%9},{%0,%1,%2,%3};" \
        : "+f"((acc)[0]), "+f"((acc)[1]), "+f"((acc)[2]), "+f"((acc)[3]) \
        : "r"((a)[0]), "r"((a)[1]), "r"((a)[2]), "r"((a)[3]), "r"(b0), "r"(b1))

// ---------------- LayerNorm gather (block-a entry only) ----------------------
template<bool GATHER>
__global__ __launch_bounds__(128) void ln_kernel(
    const float* __restrict__ x, const float* __restrict__ gam,
    const float* __restrict__ bet, __half* __restrict__ out, int shift)
{
    int lane = threadIdx.x & 31;
    int warp = threadIdx.x >> 5;
    int r = blockIdx.x * 4 + warp;
    const float* src;
    if (GATHER) {
        int wi = r >> 6, n = r & 63;
        int b  = wi / NWIN, wl = wi % NWIN;
        int whi = wl / 12, wwi = wl % 12;
        int h0 = whi * 8 + (n >> 3), w0 = wwi * 8 + (n & 7);
        int hs = h0 + shift; if (hs >= HH) hs -= HH;
        int ws_ = w0 + shift; if (ws_ >= WW) ws_ -= WW;
        src = &x[(size_t)(b * LL + hs * WW + ws_) * CC];
    } else {
        src = &x[(size_t)r * CC];
    }
    float4 v = *(const float4*)&src[lane * 4];
    float s1 = v.x + v.y + v.z + v.w;
    float s2 = v.x*v.x + v.y*v.y + v.z*v.z + v.w*v.w;
    #pragma unroll
    for (int o = 16; o; o >>= 1) {
        s1 += __shfl_xor_sync(0xffffffffu, s1, o);
        s2 += __shfl_xor_sync(0xffffffffu, s2, o);
    }
    float mean = s1 * (1.f / CC);
    float var  = s2 * (1.f / CC) - mean * mean;
    float rstd = rsqrtf(var + 1e-5f);
    float4 g4 = *(const float4*)&gam[lane * 4];
    float4 b4 = *(const float4*)&bet[lane * 4];
    float4 o4;
    o4.x = (v.x - mean) * rstd * g4.x + b4.x;
    o4.y = (v.y - mean) * rstd * g4.y + b4.y;
    o4.z = (v.z - mean) * rstd * g4.z + b4.z;
    o4.w = (v.w - mean) * rstd * g4.w + b4.w;
    *(uint2*)&out[(size_t)r * CC + lane * 4] = f4_to_h4(o4);
}

// ---------------- batched weight transpose ----------------------------------
struct TPJobs {
    const float* src[9];
    __half* dst[9];
    int K[9];
    int N[9];
};
__global__ __launch_bounds__(256) void transpose_all(TPJobs jb)
{
    __shared__ float t[32][33];
    int m = blockIdx.z;
    int K = jb.K[m], N = jb.N[m];
    int k0 = blockIdx.x * 32, n0 = blockIdx.y * 32;
    if (k0 >= K || n0 >= N) return;
    const float* src = jb.src[m];
    __half* dst = jb.dst[m];
    int x = threadIdx.x & 31, y = threadIdx.x >> 5;
    #pragma unroll
    for (int i = 0; i < 32; i += 8)
        t[y + i][x] = src[(size_t)(k0 + y + i) * N + n0 + x];
    __syncthreads();
    #pragma unroll
    for (int i = 0; i < 32; i += 8)
        dst[(size_t)(n0 + y + i) * K + k0 + x] = __float2half_rn(t[x][y + i]);
}

// ---------------- shared GEMM plumbing (k32-chunk path) ----------------------
#define AS_STRIDE 40
#define TILE_H   (128*AS_STRIDE)
#define GM_SMEM  (4*TILE_H*2)              // 40960 bytes

__device__ __forceinline__ void copy_chunk(
    const __half* __restrict__ A, const __half* __restrict__ B,
    int bm, int bn, int K, int k0, __half* sA, __half* sB, int tid)
{
    uint32_t a_s = smem_u32(sA), b_s = smem_u32(sB);
    #pragma unroll
    for (int i = 0; i < 2; i++) {
        int idx = tid + i * 256;
        int row = idx >> 2, q = idx & 3;
        const __half* ga = &A[(size_t)(bm + row) * K + k0 + q * 8];
        const __half* gb = &B[(size_t)(bn + row) * K + k0 + q * 8];
        uint32_t so = (row * AS_STRIDE + q * 8) * 2;
        asm volatile("cp.async.cg.shared.global [%0],[%1],16;" :: "r"(a_s + so), "l"(ga));
        asm volatile("cp.async.cg.shared.global [%0],[%1],16;" :: "r"(b_s + so), "l"(gb));
    }
    asm volatile("cp.async.commit_group;" ::: "memory");
}

// ---------------- general GEMM (EPI 0:+bias | 2:+bias,GELU | 4:plain) --------
template<int EPI, typename OT>
__global__ __launch_bounds__(256)
void gemm_mma(const __half* __restrict__ A, const __half* __restrict__ B,
              const float* __restrict__ bias, OT* __restrict__ C,
              const float* __restrict__ res, int M, int N, int K, int shift)
{
    extern __shared__ __half smh[];
    __half* bufA[2] = { smh,          smh + 2*TILE_H };
    __half* bufB[2] = { smh + TILE_H, smh + 3*TILE_H };
    int tid = threadIdx.x, lane = tid & 31, wid = tid >> 5;
    int g = lane >> 2, kq = lane & 3;
    int warpM = wid & 3, warpN = wid >> 2;
    int bm = blockIdx.x * 128, bn = blockIdx.y * 128;

    float acc[2][8][4];
    #pragma unroll
    for (int i = 0; i < 2; i++)
        #pragma unroll
        for (int j = 0; j < 8; j++)
            #pragma unroll
            for (int q = 0; q < 4; q++) acc[i][j][q] = 0.f;

    int nc = K >> 5;
    copy_chunk(A, B, bm, bn, K, 0, bufA[0], bufB[0], tid);

    uint32_t a_off = (((warpM * 32 + (lane & 15)) * AS_STRIDE) + ((lane >> 4) << 3)) * 2;
    uint32_t b_off = (((warpN * 64 + (lane & 7) + (((lane >> 4) & 1) << 3)) * AS_STRIDE)
                     + (((lane >> 3) & 1) << 3)) * 2;

    for (int c = 0; c < nc; c++) {
        if (c + 1 < nc) {
            copy_chunk(A, B, bm, bn, K, (c + 1) << 5, bufA[(c+1)&1], bufB[(c+1)&1], tid);
            asm volatile("cp.async.wait_group 1;" ::: "memory");
        } else {
            asm volatile("cp.async.wait_group 0;" ::: "memory");
        }
        __syncthreads();

        uint32_t ab = smem_u32(bufA[c&1]) + a_off;
        uint32_t bb = smem_u32(bufB[c&1]) + b_off;
        #pragma unroll
        for (int ks = 0; ks < 2; ks++) {
            uint32_t a[2][4], b[4][4];
            LDSM4(a[0], ab + ks * 32);
            LDSM4(a[1], ab + 16 * AS_STRIDE * 2 + ks * 32);
            #pragma unroll
            for (int j16 = 0; j16 < 4; j16++)
                LDSM4(b[j16], bb + j16 * 16 * AS_STRIDE * 2 + ks * 32);
            #pragma unroll
            for (int i = 0; i < 2; i++)
                #pragma unroll
                for (int j = 0; j < 8; j++) {
                    uint32_t b0 = b[j >> 1][(j & 1) * 2];
                    uint32_t b1 = b[j >> 1][(j & 1) * 2 + 1];
                    MMA16816(acc[i][j], a[i], b0, b1);
                }
        }
        __syncthreads();
    }

    #pragma unroll
    for (int i = 0; i < 2; i++) {
        #pragma unroll
        for (int rr = 0; rr < 2; rr++) {
            int gr = bm + warpM * 32 + i * 16 + g + rr * 8;
            #pragma unroll
            for (int j = 0; j < 8; j++) {
                int col = bn + warpN * 64 + j * 8 + 2 * kq;
                float vx = acc[i][j][rr*2+0];
                float vy = acc[i][j][rr*2+1];
                if (EPI != 4) {
                    vx += __ldg(&bias[col]);
                    vy += __ldg(&bias[col+1]);
                }
                if (EPI == 2) { vx = gelu_exact(vx); vy = gelu_exact(vy); }
                if (sizeof(OT) == 2) {
                    *(__half2*)&((__half*)C)[(size_t)gr * N + col] = __floats2half2_rn(vx, vy);
                } else {
                    *(float2*)&((float*)C)[(size_t)gr * N + col] = make_float2(vx, vy);
                }
            }
        }
    }
}

// ---------------- wide GEMM: K=128, A resident full-K, loop over N-tiles -----
#define AW_STRIDE 136                       // 128 k-halves + 8 pad
#define AW_TILE   (128*AW_STRIDE)           // halves (17408)
#define GW_SMEM   (3*AW_TILE*2)             // A + 2 B buffers = 104448 bytes

template<int EPI>
__global__ __launch_bounds__(256)
void gemm_wide(const __half* __restrict__ A, const __half* __restrict__ B,
               const float* __restrict__ bias, __half* __restrict__ C,
               int N, int nt)
{
    extern __shared__ __half smh[];
    __half* sA = smh;
    __half* sB[2] = { smh + AW_TILE, smh + 2*AW_TILE };
    int tid = threadIdx.x, lane = tid & 31, wid = tid >> 5;
    int g = lane >> 2, kq = lane & 3;
    int warpM = wid & 3, warpN = wid >> 2;
    int bm = blockIdx.x * 128;

    {
        uint32_t a_s = smem_u32(sA), b_s = smem_u32(sB[0]);
        #pragma unroll
        for (int i = 0; i < 8; i++) {
            int idx = tid + i * 256;
            int row = idx >> 4, q = idx & 15;
            uint32_t so = (row * AW_STRIDE + q * 8) * 2;
            asm volatile("cp.async.cg.shared.global [%0],[%1],16;"
                :: "r"(a_s + so), "l"(&A[(size_t)(bm + row) * 128 + q * 8]));
            asm volatile("cp.async.cg.shared.global [%0],[%1],16;"
                :: "r"(b_s + so), "l"(&B[(size_t)row * 128 + q * 8]));
        }
        asm volatile("cp.async.commit_group;" ::: "memory");
        if (nt > 1) {
            uint32_t b1_s = smem_u32(sB[1]);
            #pragma unroll
            for (int i = 0; i < 8; i++) {
                int idx = tid + i * 256;
                int row = idx >> 4, q = idx & 15;
                uint32_t so = (row * AW_STRIDE + q * 8) * 2;
                asm volatile("cp.async.cg.shared.global [%0],[%1],16;"
                    :: "r"(b1_s + so), "l"(&B[(size_t)(128 + row) * 128 + q * 8]));
            }
            asm volatile("cp.async.commit_group;" ::: "memory");
        }
    }

    uint32_t a_off = (((warpM * 32 + (lane & 15)) * AW_STRIDE) + ((lane >> 4) << 3)) * 2;
    uint32_t b_off = (((warpN * 64 + (lane & 7) + (((lane >> 4) & 1) << 3)) * AW_STRIDE)
                     + (((lane >> 3) & 1) << 3)) * 2;
    uint32_t ab = smem_u32(sA) + a_off;

    for (int bn = 0; bn < nt; bn++) {
        if (bn + 1 < nt)
            asm volatile("cp.async.wait_group 1;" ::: "memory");
        else
            asm volatile("cp.async.wait_group 0;" ::: "memory");
        __syncthreads();

        float acc[2][8][4];
        #pragma unroll
        for (int i = 0; i < 2; i++)
            #pragma unroll
            for (int j = 0; j < 8; j++)
                #pragma unroll
                for (int q = 0; q < 4; q++) acc[i][j][q] = 0.f;

        uint32_t bb = smem_u32(sB[bn & 1]) + b_off;
        #pragma unroll
        for (int ks = 0; ks < 8; ks++) {
            uint32_t a[2][4], b[4][4];
            LDSM4(a[0], ab + ks * 32);
            LDSM4(a[1], ab + 16 * AW_STRIDE * 2 + ks * 32);
            #pragma unroll
            for (int j16 = 0; j16 < 4; j16++)
                LDSM4(b[j16], bb + j16 * 16 * AW_STRIDE * 2 + ks * 32);
            #pragma unroll
            for (int i = 0; i < 2; i++)
                #pragma unroll
                for (int j = 0; j < 8; j++) {
                    uint32_t b0 = b[j >> 1][(j & 1) * 2];
                    uint32_t b1 = b[j >> 1][(j & 1) * 2 + 1];
                    MMA16816(acc[i][j], a[i], b0, b1);
                }
        }

        #pragma unroll
        for (int i = 0; i < 2; i++) {
            #pragma unroll
            for (int rr = 0; rr < 2; rr++) {
                int gr = bm + warpM * 32 + i * 16 + g + rr * 8;
                #pragma unroll
                for (int j = 0; j < 8; j++) {
                    int col = bn * 128 + warpN * 64 + j * 8 + 2 * kq;
                    float vx = acc[i][j][rr*2+0] + __ldg(&bias[col]);
                    float vy = acc[i][j][rr*2+1] + __ldg(&bias[col+1]);
                    if (EPI == 2) { vx = gelu_exact(vx); vy = gelu_exact(vy); }
                    *(__half2*)&C[(size_t)gr * N + col] = __floats2half2_rn(vx, vy);
                }
            }
        }

        if (bn + 2 < nt) {
            __syncthreads();
            uint32_t bs = smem_u32(sB[bn & 1]);
            #pragma unroll
            for (int i = 0; i < 8; i++) {
                int idx = tid + i * 256;
                int row = idx >> 4, q = idx & 15;
                uint32_t so = (row * AW_STRIDE + q * 8) * 2;
                asm volatile("cp.async.cg.shared.global [%0],[%1],16;"
                    :: "r"(bs + so), "l"(&B[(size_t)((bn + 2) * 128 + row) * 128 + q * 8]));
            }
            asm volatile("cp.async.commit_group;" ::: "memory");
        } else {
            __syncthreads();
        }
    }
}

// ---------------- N=128 GEMM with fused residual + LayerNorm -----------------
// MODE 0: proj (scatter+shift, LN->lnout spatial)
// MODE 1: fc2a (LN->lnout window-gather shift4)
// MODE 2: fc2b (no LN)
template<int MODE>
__global__ __launch_bounds__(256)
void gemm_ln(const __half* __restrict__ A, const __half* __restrict__ B,
             const float* __restrict__ bias, float* __restrict__ C,
             const float* __restrict__ res, const float* __restrict__ gam,
             const float* __restrict__ bet, __half* __restrict__ lnout,
             int K, int shift)
{
    extern __shared__ __half smh[];
    __half* bufA[2] = { smh,          smh + 2*TILE_H };
    __half* bufB[2] = { smh + TILE_H, smh + 3*TILE_H };
    int tid = threadIdx.x, lane = tid & 31, wid = tid >> 5;
    int g = lane >> 2, kq = lane & 3;
    int bm = blockIdx.x * 128;

    float acc[16][4];
    #pragma unroll
    for (int j = 0; j < 16; j++)
        #pragma unroll
        for (int q = 0; q < 4; q++) acc[j][q] = 0.f;

    int nc = K >> 5;
    copy_chunk(A, B, bm, 0, K, 0, bufA[0], bufB[0], tid);

    uint32_t a_off = (((wid * 16 + (lane & 15)) * AS_STRIDE) + ((lane >> 4) << 3)) * 2;
    uint32_t b_off = ((((lane & 7) + (((lane >> 4) & 1) << 3)) * AS_STRIDE)
                     + (((lane >> 3) & 1) << 3)) * 2;

    for (int c = 0; c < nc; c++) {
        if (c + 1 < nc) {
            copy_chunk(A, B, bm, 0, K, (c + 1) << 5, bufA[(c+1)&1], bufB[(c+1)&1], tid);
            asm volatile("cp.async.wait_group 1;" ::: "memory");
        } else {
            asm volatile("cp.async.wait_group 0;" ::: "memory");
        }
        __syncthreads();

        uint32_t ab = smem_u32(bufA[c&1]) + a_off;
        uint32_t bb = smem_u32(bufB[c&1]) + b_off;
        #pragma unroll
        for (int ks = 0; ks < 2; ks++) {
            uint32_t a[4];
            LDSM4(a, ab + ks * 32);
            #pragma unroll
            for (int j16 = 0; j16 < 8; j16++) {
                uint32_t b[4];
                LDSM4(b, bb + j16 * 16 * AS_STRIDE * 2 + ks * 32);
                MMA16816(acc[2*j16],   a, b[0], b[1]);
                MMA16816(acc[2*j16+1], a, b[2], b[3]);
            }
        }
        __syncthreads();
    }

    int r0 = bm + wid * 16 + g;
    int r1 = r0 + 8;
    int dst0, dst1;
    if (MODE == 0) {
        int d[2];
        #pragma unroll
        for (int rr = 0; rr < 2; rr++) {
            int gr = rr ? r1 : r0;
            int wi = gr >> 6, n = gr & 63;
            int b  = wi / NWIN, wl = wi % NWIN;
            int whi = wl / 12, wwi = wl % 12;
            int h0 = whi * 8 + (n >> 3), w0 = wwi * 8 + (n & 7);
            int h = h0 + shift; if (h >= HH) h -= HH;
            int w = w0 + shift; if (w >= WW) w -= WW;
            d[rr] = b * LL + h * WW + w;
        }
        dst0 = d[0]; dst1 = d[1];
    } else {
        dst0 = r0; dst1 = r1;
    }

    float vv[16][4];
    float s1a = 0.f, s2a = 0.f, s1b = 0.f, s2b = 0.f;
    #pragma unroll
    for (int j = 0; j < 16; j++) {
        int col = j * 8 + 2 * kq;
        float bx = __ldg(&bias[col]), by = __ldg(&bias[col+1]);
        float2 ra = *(const float2*)&res[(size_t)dst0 * CC + col];
        float2 rb = *(const float2*)&res[(size_t)dst1 * CC + col];
        float v0 = acc[j][0] + bx + ra.x;
        float v1 = acc[j][1] + by + ra.y;
        float v2 = acc[j][2] + bx + rb.x;
        float v3 = acc[j][3] + by + rb.y;
        vv[j][0] = v0; vv[j][1] = v1; vv[j][2] = v2; vv[j][3] = v3;
        *(float2*)&C[(size_t)dst0 * CC + col] = make_float2(v0, v1);
        *(float2*)&C[(size_t)dst1 * CC + col] = make_float2(v2, v3);
        if (MODE != 2) {
            s1a += v0 + v1; s2a += v0*v0 + v1*v1;
            s1b += v2 + v3; s2b += v2*v2 + v3*v3;
        }
    }
    if (MODE == 2) return;

    s1a += __shfl_xor_sync(0xffffffffu, s1a, 1);
    s1a += __shfl_xor_sync(0xffffffffu, s1a, 2);
    s2a += __shfl_xor_sync(0xffffffffu, s2a, 1);
    s2a += __shfl_xor_sync(0xffffffffu, s2a, 2);
    s1b += __shfl_xor_sync(0xffffffffu, s1b, 1);
    s1b += __shfl_xor_sync(0xffffffffu, s1b, 2);
    s2b += __shfl_xor_sync(0xffffffffu, s2b, 1);
    s2b += __shfl_xor_sync(0xffffffffu, s2b, 2);

    float ma = s1a * (1.f/CC), va = s2a * (1.f/CC) - ma*ma;
    float mb = s1b * (1.f/CC), vb = s2b * (1.f/CC) - mb*mb;
    float ra_ = rsqrtf(va + 1e-5f), rb_ = rsqrtf(vb + 1e-5f);

    int ln0, ln1;
    if (MODE == 0) { ln0 = dst0; ln1 = dst1; }
    else {
        int d[2];
        #pragma unroll
        for (int rr = 0; rr < 2; rr++) {
            int gr = rr ? r1 : r0;
            int b = gr / LL, rem = gr % LL;
            int h = rem / WW, w = rem % WW;
            int h0 = h - 4; if (h0 < 0) h0 += HH;
            int w0 = w - 4; if (w0 < 0) w0 += WW;
            d[rr] = b * LL + ((h0 >> 3) * 12 + (w0 >> 3)) * 64 + (h0 & 7) * 8 + (w0 & 7);
        }
        ln0 = d[0]; ln1 = d[1];
    }

    #pragma unroll
    for (int j = 0; j < 16; j++) {
        int col = j * 8 + 2 * kq;
        float gx = __ldg(&gam[col]), gy = __ldg(&gam[col+1]);
        float bx = __ldg(&bet[col]), by = __ldg(&bet[col+1]);
        *(__half2*)&lnout[(size_t)ln0 * CC + col] =
            __floats2half2_rn((vv[j][0]-ma)*ra_*gx+bx, (vv[j][1]-ma)*ra_*gy+by);
        *(__half2*)&lnout[(size_t)ln1 * CC + col] =
            __floats2half2_rn((vv[j][2]-mb)*rb_*gx+bx, (vv[j][3]-mb)*rb_*gy+by);
    }
}

// ---------------- MMA windowed attention (stride 392, K frags hoisted) -------
#define AT_STRIDE 392
#define AT_SMEM   (64*AT_STRIDE*2 + 64*4)   // 50432 bytes

template<bool SHIFTED>
__global__ __launch_bounds__(128) void attn_mma(
    const __half* __restrict__ qkv, __half* __restrict__ out)
{
    extern __shared__ __half smw[];
    int* lab = (int*)(smw + 64*AT_STRIDE);
    int tid = threadIdx.x, lane = tid & 31, h = tid >> 5;
    int wi = blockIdx.x;

    const uint4* gsrc = (const uint4*)(qkv + (size_t)wi * 64 * 384);
    #pragma unroll
    for (int i = 0; i < 24; i++) {
        int idx = tid + i * 128;
        int row = idx / 48, seg = idx % 48;
        *(uint4*)&smw[row * AT_STRIDE + seg * 8] = gsrc[row * 48 + seg];
    }
    if (SHIFTED && tid < 64) {
        int wl = wi % NWIN;
        int whi = wl / 12, wwi = wl % 12;
        int hh = whi * 8 + (tid >> 3), ww_ = wwi * 8 + (tid & 7);
        int hr = (hh < HH - WS) ? 0 : ((hh < HH - 4) ? 1 : 2);
        int wr = (ww_ < WW - WS) ? 0 : ((ww_ < WW - 4) ? 1 : 2);
        lab[tid] = hr * 3 + wr;
    }
    __syncthreads();

    uint32_t sbase = smem_u32(smw);
    int qbase = h * 32;
    int kbase = 128 + h * 32;
    int vbase = 256 + h * 32;

    uint32_t q_row  = lane & 15;
    uint32_t q_colh = (lane >> 4) << 3;
    uint32_t k_row  = (lane & 7) + (((lane >> 4) & 1) << 3);
    uint32_t k_colh = ((lane >> 3) & 1) << 3;
    uint32_t v_row  = lane & 15;
    uint32_t v_colh = (lane >> 4) << 3;

    // hoist K fragments (invariant across mt): [kt][j16][4]
    uint32_t kf[2][4][4];
    #pragma unroll
    for (int kt = 0; kt < 2; kt++)
        #pragma unroll
        for (int j16 = 0; j16 < 4; j16++)
            LDSM4(kf[kt][j16],
                  sbase + ((j16*16 + k_row) * AT_STRIDE + kbase + k_colh + kt*16) * 2);

    #pragma unroll
    for (int mt = 0; mt < 4; mt++) {
        float sAcc[8][4];
        #pragma unroll
        for (int j = 0; j < 8; j++)
            #pragma unroll
            for (int q = 0; q < 4; q++) sAcc[j][q] = 0.f;
        #pragma unroll
        for (int kt = 0; kt < 2; kt++) {
            uint32_t a[4];
            LDSM4(a, sbase + ((mt*16 + q_row) * AT_STRIDE + qbase + q_colh + kt*16) * 2);
            #pragma unroll
            for (int j16 = 0; j16 < 4; j16++) {
                MMA16816(sAcc[2*j16],   a, kf[kt][j16][0], kf[kt][j16][1]);
                MMA16816(sAcc[2*j16+1], a, kf[kt][j16][2], kf[kt][j16][3]);
            }
        }

        int row_lo = mt*16 + (lane >> 2);
        int row_hi = row_lo + 8;
        if (SHIFTED) {
            int ll = lab[row_lo], lh = lab[row_hi];
            #pragma unroll
            for (int j = 0; j < 8; j++) {
                int c0 = j*8 + 2*(lane & 3);
                int lc0 = lab[c0], lc1 = lab[c0+1];
                if (lc0 != ll) sAcc[j][0] = -1e30f;
                if (lc1 != ll) sAcc[j][1] = -1e30f;
                if (lc0 != lh) sAcc[j][2] = -1e30f;
                if (lc1 != lh) sAcc[j][3] = -1e30f;
            }
        }
        float mlo = -1e30f, mhi = -1e30f;
        #pragma unroll
        for (int j = 0; j < 8; j++) {
            mlo = fmaxf(mlo, fmaxf(sAcc[j][0], sAcc[j][1]));
            mhi = fmaxf(mhi, fmaxf(sAcc[j][2], sAcc[j][3]));
        }
        mlo = fmaxf(mlo, __shfl_xor_sync(0xffffffffu, mlo, 1));
        mlo = fmaxf(mlo, __shfl_xor_sync(0xffffffffu, mlo, 2));
        mhi = fmaxf(mhi, __shfl_xor_sync(0xffffffffu, mhi, 1));
        mhi = fmaxf(mhi, __shfl_xor_sync(0xffffffffu, mhi, 2));
        float slo = 0.f, shi = 0.f;
        uint32_t pf[8][2];
        #pragma unroll
        for (int j = 0; j < 8; j++) {
            float e0 = __expf((sAcc[j][0] - mlo) * QKSCALE);
            float e1 = __expf((sAcc[j][1] - mlo) * QKSCALE);
            float e2 = __expf((sAcc[j][2] - mhi) * QKSCALE);
            float e3 = __expf((sAcc[j][3] - mhi) * QKSCALE);
            slo += e0 + e1; shi += e2 + e3;
            pf[j][0] = h2pack(e0, e1);
            pf[j][1] = h2pack(e2, e3);
        }
        slo += __shfl_xor_sync(0xffffffffu, slo, 1);
        slo += __shfl_xor_sync(0xffffffffu, slo, 2);
        shi += __shfl_xor_sync(0xffffffffu, shi, 1);
        shi += __shfl_xor_sync(0xffffffffu, shi, 2);
        float ilo = 1.f / slo, ihi = 1.f / shi;

        float oAcc[4][4];
        #pragma unroll
        for (int j = 0; j < 4; j++)
            #pragma unroll
            for (int q = 0; q < 4; q++) oAcc[j][q] = 0.f;
        #pragma unroll
        for (int t = 0; t < 4; t++) {
            uint32_t a[4] = { pf[2*t][0], pf[2*t][1], pf[2*t+1][0], pf[2*t+1][1] };
            #pragma unroll
            for (int n16 = 0; n16 < 2; n16++) {
                uint32_t b[4];
                LDSM4T(b, sbase + ((t*16 + v_row) * AT_STRIDE + vbase + n16*16 + v_colh) * 2);
                MMA16816(oAcc[2*n16],   a, b[0], b[1]);
                MMA16816(oAcc[2*n16+1], a, b[2], b[3]);
            }
        }

        __half* orow_lo = &out[(size_t)(wi*64 + row_lo) * CC + h*32];
        __half* orow_hi = &out[(size_t)(wi*64 + row_hi) * CC + h*32];
        #pragma unroll
        for (int j = 0; j < 4; j++) {
            int col = j*8 + 2*(lane & 3);
            *(__half2*)&orow_lo[col] = __floats2half2_rn(oAcc[j][0]*ilo, oAcc[j][1]*ilo);
            *(__half2*)&orow_hi[col] = __floats2half2_rn(oAcc[j][2]*ihi, oAcc[j][3]*ihi);
        }
    }
}

// ---------------- patch-merge gather + LN(512), half out --------------------
__global__ __launch_bounds__(128) void pm_ln_kernel(
    const float* __restrict__ x, const float* __restrict__ gam,
    const float* __restrict__ bet, __half* __restrict__ out)
{
    int lane = threadIdx.x & 31;
    int warp = threadIdx.x >> 5;
    int i = blockIdx.x * 4 + warp;
    int b = i / 2304, pos = i % 2304;
    int oh = pos / 48, ow = pos % 48;
    int base = b * LL;
    int src[4];
    src[0] = base + (2*oh    ) * WW + 2*ow;
    src[1] = base + (2*oh + 1) * WW + 2*ow;
    src[2] = base + (2*oh    ) * WW + 2*ow + 1;
    src[3] = base + (2*oh + 1) * WW + 2*ow + 1;
    float4 v[4];
    float s1 = 0.f, s2 = 0.f;
    #pragma unroll
    for (int k = 0; k < 4; k++) {
        v[k] = *(const float4*)&x[(size_t)src[k] * CC + lane * 4];
        s1 += v[k].x + v[k].y + v[k].z + v[k].w;
        s2 += v[k].x*v[k].x + v[k].y*v[k].y + v[k].z*v[k].z + v[k].w*v[k].w;
    }
    #pragma unroll
    for (int o = 16; o; o >>= 1) {
        s1 += __shfl_xor_sync(0xffffffffu, s1, o);
        s2 += __shfl_xor_sync(0xffffffffu, s2, o);
    }
    float mean = s1 * (1.f / 512.f);
    float var  = s2 * (1.f / 512.f) - mean * mean;
    float rstd = rsqrtf(var + 1e-5f);
    #pragma unroll
    for (int k = 0; k < 4; k++) {
        int col = k * CC + lane * 4;
        float4 g4 = *(const float4*)&gam[col];
        float4 b4 = *(const float4*)&bet[col];
        float4 o4;
        o4.x = (v[k].x - mean) * rstd * g4.x + b4.x;
        o4.y = (v[k].y - mean) * rstd * g4.y + b4.y;
        o4.z = (v[k].z - mean) * rstd * g4.z + b4.z;
        o4.w = (v[k].w - mean) * rstd * g4.w + b4.w;
        *(uint2*)&out[(size_t)i * 512 + col] = f4_to_h4(o4);
    }
}

// ---------------- host orchestration ----------------------------------------
extern "C" void kernel_launch(void* const* d_in, const int* in_sizes, int n_in,
                              void* d_out, int out_size)
{
    (void)in_sizes; (void)n_in; (void)out_size;
    const float* x = (const float*)d_in[0];
    const float* pa[12];
    const float* pb[12];
    for (int i = 0; i < 12; i++) pa[i] = (const float*)d_in[1 + i];
    for (int i = 0; i < 12; i++) pb[i] = (const float*)d_in[13 + i];
    const float* mln_g = (const float*)d_in[25];
    const float* mln_b = (const float*)d_in[26];
    const float* red_w = (const float*)d_in[27];
    float* out = (float*)d_out;

    __half *xw, *qkv, *att, *h, *wt;
    float *xa, *xb;
    cudaGetSymbolAddress((void**)&xw,  g_xw);
    cudaGetSymbolAddress((void**)&qkv, g_qkv);
    cudaGetSymbolAddress((void**)&att, g_att);
    cudaGetSymbolAddress((void**)&xa,  g_xa);
    cudaGetSymbolAddress((void**)&xb,  g_xb);
    cudaGetSymbolAddress((void**)&h,   g_h);
    cudaGetSymbolAddress((void**)&wt,  g_wt);

    static bool attr_done = false;
    if (!attr_done) {
        cudaFuncSetAttribute(attn_mma<false>, cudaFuncAttributeMaxDynamicSharedMemorySize, AT_SMEM);
        cudaFuncSetAttribute(attn_mma<true>,  cudaFuncAttributeMaxDynamicSharedMemorySize, AT_SMEM);
        cudaFuncSetAttribute(gemm_wide<0>, cudaFuncAttributeMaxDynamicSharedMemorySize, GW_SMEM);
        cudaFuncSetAttribute(gemm_wide<2>, cudaFuncAttributeMaxDynamicSharedMemorySize, GW_SMEM);
        attr_done = true;
    }

    __half* a_qkv_t  = wt;
    __half* a_proj_t = wt + 49152;
    __half* a_fc1_t  = wt + 65536;
    __half* a_fc2_t  = wt + 131072;
    __half* b_qkv_t  = wt + 196608;
    __half* b_proj_t = wt + 245760;
    __half* b_fc1_t  = wt + 262144;
    __half* b_fc2_t  = wt + 327680;
    __half* red_t    = wt + 393216;

    TPJobs jb;
    jb.src[0] = pa[2];  jb.dst[0] = a_qkv_t;  jb.K[0] = 128; jb.N[0] = 384;
    jb.src[1] = pa[4];  jb.dst[1] = a_proj_t; jb.K[1] = 128; jb.N[1] = 128;
    jb.src[2] = pa[8];  jb.dst[2] = a_fc1_t;  jb.K[2] = 128; jb.N[2] = 512;
    jb.src[3] = pa[10]; jb.dst[3] = a_fc2_t;  jb.K[3] = 512; jb.N[3] = 128;
    jb.src[4] = pb[2];  jb.dst[4] = b_qkv_t;  jb.K[4] = 128; jb.N[4] = 384;
    jb.src[5] = pb[4];  jb.dst[5] = b_proj_t; jb.K[5] = 128; jb.N[5] = 128;
    jb.src[6] = pb[8];  jb.dst[6] = b_fc1_t;  jb.K[6] = 128; jb.N[6] = 512;
    jb.src[7] = pb[10]; jb.dst[7] = b_fc2_t;  jb.K[7] = 512; jb.N[7] = 128;
    jb.src[8] = red_w;  jb.dst[8] = red_t;    jb.K[8] = 512; jb.N[8] = 256;
    transpose_all<<<dim3(16, 16, 9), 256>>>(jb);

    // ---------------- block a (shift 0) ----------------
    ln_kernel<true><<<ROWS/4, 128>>>(x, pa[0], pa[1], xw, 0);
    gemm_wide<0><<<ROWS/128, 256, GW_SMEM>>>(xw, a_qkv_t, pa[3], qkv, 384, 3);
    attn_mma<false><<<ROWS/NTOK, 128, AT_SMEM>>>(qkv, att);
    gemm_ln<0><<<ROWS/128, 256, GM_SMEM>>>(att, a_proj_t, pa[5], xa, x, pa[6], pa[7], xw, CC, 0);
    gemm_wide<2><<<ROWS/128, 256, GW_SMEM>>>(xw, a_fc1_t, pa[9], h, 512, 4);
    gemm_ln<1><<<ROWS/128, 256, GM_SMEM>>>(h, a_fc2_t, pa[11], xa, xa, pb[0], pb[1], xw, 512, 4);

    // ---------------- block b (shift 4) ----------------
    gemm_wide<0><<<ROWS/128, 256, GW_SMEM>>>(xw, b_qkv_t, pb[3], qkv, 384, 3);
    attn_mma<true><<<ROWS/NTOK, 128, AT_SMEM>>>(qkv, att);
    gemm_ln<0><<<ROWS/128, 256, GM_SMEM>>>(att, b_proj_t, pb[5], xb, xa, pb[6], pb[7], xw, CC, 4);
    gemm_wide<2><<<ROWS/128, 256, GW_SMEM>>>(xw, b_fc1_t, pb[9], h, 512, 4);
    gemm_ln<2><<<ROWS/128, 256, GM_SMEM>>>(h, b_fc2_t, pb[11], xb, xb, nullptr, nullptr, nullptr, 512, 0);

    // ---------------- patch merge ----------------
    pm_ln_kernel<<<(ROWS/4)/NTOK * 16, 128>>>(xb, mln_g, mln_b, att);
    gemm_mma<4,float><<<dim3((ROWS/4)/128, 2), 256, GM_SMEM>>>(att, red_t, nullptr, out, nullptr,
                                                               ROWS/4, 256, 512, 0);
}